// round 8
// baseline (speedup 1.0000x reference)
#include <cuda_runtime.h>
#include <cuda_bf16.h>
#include <math.h>

#define Nn 1024
#define Qq 32
#define Mm 256
#define Dd 32
#define JITTER 1e-6f
#define TRI (Mm*(Mm+1)/2)

__device__ __forceinline__ int off(int i){ return (i*(i+1))>>1; }

// ---------------- scratch ----------------
__device__ float g_hw1[Nn*Qq];
__device__ float g_wm1[Nn*Qq];
__device__ float g_hw2[Nn*Qq];
__device__ float g_w2[Nn*Qq];
__device__ float g_wm2[Nn*Qq];
__device__ float g_G1[Nn];
__device__ float g_F2[Nn];
__device__ float g_E2[Nn*Mm];
__device__ float g_qmk[Mm*Mm];
__device__ float g_Kmm[Mm*Mm];
__device__ float g_Lp[TRI];
__device__ float g_Ldiag[Mm];
__device__ float g_T128[128*128];
__device__ float g_Linv[Mm*Mm];
__device__ float g_Kinv[Mm*Mm];
__device__ float g_psi1[Nn*Mm];
__device__ float g_psi2[Mm*Mm];
__device__ float g_psi2p[8*Mm*Mm];
__device__ float g_A1[Nn*Mm];
__device__ float g_R[Mm*Mm*Dd];
__device__ float g_uuT[Mm*Mm];
__device__ float g_uuTp[32*Mm*Mm];
__device__ float g_Gp[8*Mm*Mm];
__device__ float g_P2[Mm*Mm];
__device__ float g_KPK[Mm*Mm];
__device__ float g_G[Mm*Mm];
__device__ float g_tmpF[(size_t)Nn*Mm*Dd];

// ---------------- per-n prep ----------------
__global__ void prep_n_kernel(const float* __restrict__ Xmean,
                              const float* __restrict__ Xvar,
                              const float* __restrict__ ls)
{
    int n = blockIdx.x*blockDim.x + threadIdx.x;
    if (n >= Nn) return;
    float ld1 = 0.f, ld2 = 0.f, a1 = 0.f, a2 = 0.f;
    #pragma unroll
    for (int q = 0; q < Qq; q++){
        float l = ls[q];
        float l2 = l*l;
        float S = Xvar[n*Qq+q];
        float mu = Xmean[n*Qq+q];
        float d1 = l2 + S;
        float d2 = l2 + 2.f*S;
        float w1 = 1.f/d1;
        float w2 = 1.f/d2;
        g_hw1[n*Qq+q] = 0.5f*w1;
        g_hw2[n*Qq+q] = 0.5f*w2;
        g_w2[n*Qq+q]  = w2;
        g_wm1[n*Qq+q] = w1*mu;
        g_wm2[n*Qq+q] = w2*mu;
        ld1 += logf(d1/l2);
        ld2 += logf(d2/l2);
        a1 = fmaf(w1*mu, mu, a1);
        a2 = fmaf(w2*mu, mu, a2);
    }
    g_G1[n] = -0.5f*ld1 - 0.5f*a1;
    g_F2[n] = -0.5f*ld2 - a2;
}

// ---------------- qmk and Kmm ----------------
__global__ void prep_kmm_kernel(const float* __restrict__ Z,
                                const float* __restrict__ ls,
                                const float* __restrict__ var_p)
{
    int idx = blockIdx.x*blockDim.x + threadIdx.x;
    if (idx >= Mm*Mm) return;
    int m = idx / Mm, k = idx % Mm;
    float s = 0.f;
    #pragma unroll
    for (int q = 0; q < Qq; q++){
        float l = ls[q];
        float d = Z[m*Qq+q] - Z[k*Qq+q];
        s += (d*d)/(l*l);
    }
    g_qmk[idx] = s;
    float v = var_p[0];
    g_Kmm[idx] = v*expf(-0.5f*s) + ((m==k)?JITTER:0.f);
}

// ---------------- fused E2 + psi1 ----------------
__global__ void e2psi1_kernel(const float* __restrict__ Z,
                              const float* __restrict__ var_p)
{
    int tx = threadIdx.x, ty = threadIdx.y;
    int m = blockIdx.x*32 + tx;
    int n0 = blockIdx.y*8;
    int n = n0 + ty;
    __shared__ float Zs[32][33];
    __shared__ float w1b[8][32], wm1b[8][32];
    __shared__ float w2b[8][32], wm2b[8][32], gs[8];
    int t = ty*32 + tx;
    for (int i = t; i < 32*Qq; i += 256){
        int r = i/Qq, q = i%Qq;
        Zs[r][q] = Z[(blockIdx.x*32+r)*Qq + q];
    }
    for (int i = t; i < 8*Qq; i += 256){
        int r = i/Qq, q = i%Qq;
        w1b[r][q]  = g_hw1[(n0+r)*Qq + q];
        wm1b[r][q] = g_wm1[(n0+r)*Qq + q];
        w2b[r][q]  = g_w2[(n0+r)*Qq + q];
        wm2b[r][q] = g_wm2[(n0+r)*Qq + q];
    }
    if (t < 8) gs[t] = g_G1[n0+t];
    __syncthreads();
    float s1 = 0.f, s2 = 0.f;
    #pragma unroll
    for (int q = 0; q < Qq; q++){
        float z = Zs[tx][q];
        float t1 = fmaf(-w1b[ty][q], z, wm1b[ty][q]);
        s1 = fmaf(t1, z, s1);
        float t2 = fmaf(-0.25f*w2b[ty][q], z, wm2b[ty][q]);
        s2 = fmaf(t2, z, s2);
    }
    g_psi1[n*Mm + m] = var_p[0]*__expf(gs[ty] + s1);
    g_E2[n*Mm + m] = s2;
}

// ---------------- psi2 ----------------
__global__ void psi2_kernel(const float* __restrict__ Z)
{
    int rem = blockIdx.x, bi = 0;
    for (bi = 0; bi < 16; bi++){ int len = 16-bi; if (rem < len) break; rem -= len; }
    int bj = bi + rem;
    int chunk = blockIdx.y;
    int tx = threadIdx.x, ty = threadIdx.y;
    int m = bi*16 + ty;
    int k = bj*16 + tx;
    int t = ty*16 + tx;

    __shared__ float Zm[16][33], Zk[16][33];
    for (int i = t; i < 16*Qq; i += 256){
        int r = i/Qq, q = i%Qq;
        Zm[r][q] = Z[(bi*16+r)*Qq + q];
        Zk[r][q] = Z[(bj*16+r)*Qq + q];
    }
    __syncthreads();
    float zp[Qq];
    #pragma unroll
    for (int q = 0; q < Qq; q++) zp[q] = Zm[ty][q]*Zk[tx][q];
    float base = -0.25f*g_qmk[m*Mm + k];

    __shared__ float wb[16][33], F2s[16];
    __shared__ float Em[16][17], Ek[16][17];
    float acc = 0.f;
    int nbeg = chunk*(Nn/8), nend = nbeg + Nn/8;
    for (int n0 = nbeg; n0 < nend; n0 += 16){
        __syncthreads();
        for (int i = t; i < 16*Qq; i += 256){
            int r = i/Qq, q = i%Qq;
            wb[r][q] = g_hw2[(n0+r)*Qq + q];
        }
        {
            int nn = t >> 4, r = t & 15;
            Em[nn][r] = g_E2[(n0+nn)*Mm + bi*16 + r];
            Ek[nn][r] = g_E2[(n0+nn)*Mm + bj*16 + r];
        }
        if (t < 16) F2s[t] = g_F2[n0+t];
        __syncthreads();
        #pragma unroll 2
        for (int nn = 0; nn < 16; nn++){
            float dot = 0.f;
            #pragma unroll
            for (int q = 0; q < Qq; q++)
                dot = fmaf(wb[nn][q], zp[q], dot);
            float e = base + F2s[nn] + Em[nn][ty] + Ek[nn][tx] - dot;
            acc += __expf(e);
        }
    }
    g_psi2p[chunk*(Mm*Mm) + m*Mm + k] = acc;
}

__global__ void psi2_combine_kernel(const float* __restrict__ var_p)
{
    int idx = blockIdx.x*blockDim.x + threadIdx.x;
    if (idx >= Mm*Mm) return;
    int m = idx / Mm, k = idx % Mm;
    int src = ((m>>4) <= (k>>4)) ? (m*Mm + k) : (k*Mm + m);
    float s = 0.f;
    #pragma unroll
    for (int c = 0; c < 8; c++) s += g_psi2p[c*(Mm*Mm) + src];
    float v = var_p[0];
    g_psi2[idx] = v*v*s;
}

// ============ Cholesky (1024 thr) + 32-block diag inversion + level-1 ============
__global__ void cholinv_kernel()
{
    extern __shared__ float sm[];
    float* sL = sm;            // TRI
    float* Vt = sm + TRI;      // 8448
    __shared__ float col1[Mm], col2[Mm];
    int t = threadIdx.x;       // 1024 threads
    int warp = t >> 5, lane = t & 31;

    for (int idx = t; idx < TRI; idx += 1024){
        int i = (int)((sqrtf(8.f*(float)idx + 1.f) - 1.f)*0.5f);
        while (off(i+1) <= idx) i++;
        while (off(i) > idx) i--;
        int j = idx - off(i);
        sL[idx] = g_Kmm[i*Mm + j];
    }
    __syncthreads();

    for (int k = 0; k < Mm; k += 2){
        if (t == 0) sL[off(k)+k] = sqrtf(sL[off(k)+k]);
        __syncthreads();
        float invk = 1.f/sL[off(k)+k];
        float v1 = 0.f;
        if (t > k && t < Mm){ v1 = sL[off(t)+k]*invk; sL[off(t)+k] = v1; }
        if (t < Mm) col1[t] = v1;
        __syncthreads();
        float tmp = 0.f;
        if (t >= k+1 && t < Mm) tmp = sL[off(t)+(k+1)] - col1[t]*col1[k+1];
        if (t == k+1) sL[off(k+1)+(k+1)] = sqrtf(tmp);
        __syncthreads();
        float inv2 = 1.f/sL[off(k+1)+(k+1)];
        float v2 = 0.f;
        if (t > k+1 && t < Mm){ v2 = tmp*inv2; sL[off(t)+(k+1)] = v2; }
        if (t < Mm) col2[t] = v2;
        __syncthreads();
        for (int i = k+2+warp; i < Mm; i += 32){
            float ci1 = col1[i], ci2 = col2[i];
            int b = off(i);
            for (int j = k+2+lane; j <= i; j += 32)
                sL[b+j] -= ci1*col1[j] + ci2*col2[j];
        }
        __syncthreads();
    }
    if (t < Mm) g_Ldiag[t] = sL[off(t)+t];
    __syncthreads();

    // invert 8 diagonal 32x32 blocks (warps 0..7)
    if (warp < 8){
        int r0 = warp*32;
        float* V = Vt + warp*1056;
        int c = lane;
        for (int r = 0; r < 32; r++){
            float sum = 0.f;
            for (int k = c; k < r; k++)
                sum = fmaf(sL[off(r0+r)+r0+k], V[k*33+c], sum);
            float diag = sL[off(r0+r)+r0+r];
            float v;
            if (c < r)       v = -sum/diag;
            else if (c == r) v = 1.f/diag;
            else             v = 0.f;
            V[r*33+c] = v;
        }
    }
    __syncthreads();
    {
        int r = (t >> 5) & 31, c = t & 31;
        if (r < 32){
            for (int b = t >> 10; b < 8; b += 1){
                // 1024 threads: 32 warps -> (warp%32) rows, all 8 blocks sequential
            }
        }
    }
    // copy inverted diag blocks back (1024 threads: t -> (block, row, col))
    {
        int pos = t;                 // 0..1023 = 32 rows x 32 cols
        int r = pos >> 5, c = pos & 31;
        for (int b = 0; b < 8; b++)
            if (c <= r) sL[off(b*32+r)+b*32+c] = Vt[b*1056 + r*33 + c];
    }
    __syncthreads();

    // level-1 combine: 4 pairs concurrently (p = t>>8)
    {
        int p  = t >> 8;
        int ti = t & 255;
        int i  = ti >> 3;
        int j0 = (ti & 7)*4;
        int row0 = p*64;
        float acc[4] = {0,0,0,0};
        for (int k = 0; k < 32; k++){
            float b = sL[off(row0+32+i)+row0+k];
            #pragma unroll
            for (int jj = 0; jj < 4; jj++){
                int j = j0+jj;
                if (j <= k) acc[jj] = fmaf(b, sL[off(row0+k)+row0+j], acc[jj]);
            }
        }
        float* Tp = Vt + p*1056;
        #pragma unroll
        for (int jj = 0; jj < 4; jj++) Tp[i*33 + j0+jj] = acc[jj];
        __syncthreads();
        float acc2[4] = {0,0,0,0};
        for (int k = 0; k <= i; k++){
            float cv = sL[off(row0+32+i)+row0+32+k];
            #pragma unroll
            for (int jj = 0; jj < 4; jj++)
                acc2[jj] = fmaf(cv, Tp[k*33 + j0+jj], acc2[jj]);
        }
        __syncthreads();
        #pragma unroll
        for (int jj = 0; jj < 4; jj++)
            sL[off(row0+32+i)+row0+j0+jj] = -acc2[jj];
    }
    __syncthreads();

    for (int idx = t; idx < TRI; idx += 1024) g_Lp[idx] = sL[idx];
}

// ============ level-2 combine (64->128), smem-staged, 2 CTAs ============
__global__ void inv_lvl2_kernel()
{
    extern __shared__ float sm[];
    float* sA = sm;             // 64*65
    float* sB = sm + 4160;      // 64*65
    float* sT = sm + 8320;      // 64*65
    int row0 = blockIdx.x*128;
    int t = threadIdx.x;
    int lr = t >> 2, q = (t & 3)*16;
    for (int c = 0; c < 16; c++){
        int col = q + c;
        sB[lr*65 + col] = g_Lp[off(row0+64+lr) + row0 + col];
        sA[lr*65 + col] = (col <= lr) ? g_Lp[off(row0+lr) + row0 + col] : 0.f;
    }
    __syncthreads();
    int i0 = (t >> 4)*4, j0 = (t & 15)*4;
    float acc[4][4] = {};
    for (int k = 0; k < 64; k++){
        float b[4], a[4];
        #pragma unroll
        for (int ii = 0; ii < 4; ii++) b[ii] = sB[(i0+ii)*65 + k];
        #pragma unroll
        for (int jj = 0; jj < 4; jj++) a[jj] = sA[k*65 + j0+jj];
        #pragma unroll
        for (int ii = 0; ii < 4; ii++)
            #pragma unroll
            for (int jj = 0; jj < 4; jj++)
                acc[ii][jj] = fmaf(b[ii], a[jj], acc[ii][jj]);
    }
    #pragma unroll
    for (int ii = 0; ii < 4; ii++)
        #pragma unroll
        for (int jj = 0; jj < 4; jj++)
            sT[(i0+ii)*65 + j0+jj] = acc[ii][jj];
    __syncthreads();
    for (int c = 0; c < 16; c++){
        int col = q + c;
        sB[lr*65 + col] = (col <= lr) ? g_Lp[off(row0+64+lr) + row0+64 + col] : 0.f;
    }
    __syncthreads();
    float acc2[4][4] = {};
    for (int k = 0; k < 64; k++){
        float cv[4], tv[4];
        #pragma unroll
        for (int ii = 0; ii < 4; ii++) cv[ii] = sB[(i0+ii)*65 + k];
        #pragma unroll
        for (int jj = 0; jj < 4; jj++) tv[jj] = sT[k*65 + j0+jj];
        #pragma unroll
        for (int ii = 0; ii < 4; ii++)
            #pragma unroll
            for (int jj = 0; jj < 4; jj++)
                acc2[ii][jj] = fmaf(cv[ii], tv[jj], acc2[ii][jj]);
    }
    #pragma unroll
    for (int ii = 0; ii < 4; ii++)
        #pragma unroll
        for (int jj = 0; jj < 4; jj++)
            g_Lp[off(row0+64+i0+ii)+row0+j0+jj] = -acc2[ii][jj];
}

// ============ level-3a: T128 = B * Ainv(128), 4 CTAs ============
__global__ void inv_lvl3a_kernel()
{
    __shared__ float sB[64*33];
    __shared__ float sA[32*65];
    int bi = (blockIdx.x >> 1)*64, bj = (blockIdx.x & 1)*64;
    int t = threadIdx.x;
    int i0 = (t >> 4)*4, j0 = (t & 15)*4;
    float acc[4][4] = {};
    for (int kc = 0; kc < 128; kc += 32){
        __syncthreads();
        {
            int lr = t >> 2, q = (t & 3)*8;
            for (int c = 0; c < 8; c++)
                sB[lr*33 + q + c] = g_Lp[off(128 + bi + lr) + kc + q + c];
            int kr = t >> 3, q2 = (t & 7)*8;
            for (int c = 0; c < 8; c++){
                int j = bj + q2 + c;
                sA[kr*65 + q2 + c] = (j <= kc+kr) ? g_Lp[off(kc+kr) + j] : 0.f;
            }
        }
        __syncthreads();
        #pragma unroll
        for (int k = 0; k < 32; k++){
            float b[4], a[4];
            #pragma unroll
            for (int ii = 0; ii < 4; ii++) b[ii] = sB[(i0+ii)*33 + k];
            #pragma unroll
            for (int jj = 0; jj < 4; jj++) a[jj] = sA[k*65 + j0+jj];
            #pragma unroll
            for (int ii = 0; ii < 4; ii++)
                #pragma unroll
                for (int jj = 0; jj < 4; jj++)
                    acc[ii][jj] = fmaf(b[ii], a[jj], acc[ii][jj]);
        }
    }
    #pragma unroll
    for (int ii = 0; ii < 4; ii++)
        #pragma unroll
        for (int jj = 0; jj < 4; jj++)
            g_T128[(bi+i0+ii)*128 + bj+j0+jj] = acc[ii][jj];
}

// ============ level-3b: O = -Cinv(128) * T128, 4 CTAs ============
__global__ void inv_lvl3b_kernel()
{
    __shared__ float sC[64*33];
    __shared__ float sT[32*65];
    int bi = (blockIdx.x >> 1)*64, bj = (blockIdx.x & 1)*64;
    int t = threadIdx.x;
    int i0 = (t >> 4)*4, j0 = (t & 15)*4;
    float acc[4][4] = {};
    for (int kc = 0; kc < 128; kc += 32){
        __syncthreads();
        {
            int lr = t >> 2, q = (t & 3)*8;
            for (int c = 0; c < 8; c++){
                int k = kc + q + c;
                sC[lr*33 + q + c] = (k <= bi+lr) ? g_Lp[off(128 + bi + lr) + 128 + k] : 0.f;
            }
            int kr = t >> 3, q2 = (t & 7)*8;
            for (int c = 0; c < 8; c++)
                sT[kr*65 + q2 + c] = g_T128[(kc+kr)*128 + bj + q2 + c];
        }
        __syncthreads();
        #pragma unroll
        for (int k = 0; k < 32; k++){
            float cv[4], tv[4];
            #pragma unroll
            for (int ii = 0; ii < 4; ii++) cv[ii] = sC[(i0+ii)*33 + k];
            #pragma unroll
            for (int jj = 0; jj < 4; jj++) tv[jj] = sT[k*65 + j0+jj];
            #pragma unroll
            for (int ii = 0; ii < 4; ii++)
                #pragma unroll
                for (int jj = 0; jj < 4; jj++)
                    acc[ii][jj] = fmaf(cv[ii], tv[jj], acc[ii][jj]);
        }
    }
    #pragma unroll
    for (int ii = 0; ii < 4; ii++)
        #pragma unroll
        for (int jj = 0; jj < 4; jj++)
            g_Lp[off(128+bi+i0+ii) + bj+j0+jj] = -acc[ii][jj];
}

__global__ void unpack_linv_kernel()
{
    int idx = blockIdx.x*blockDim.x + threadIdx.x;
    if (idx >= Mm*Mm) return;
    int i = idx / Mm, j = idx % Mm;
    g_Linv[idx] = (j <= i) ? g_Lp[off(i)+j] : 0.f;
}

// ---------------- masked R ----------------
__global__ void maskR_kernel(const float* __restrict__ qs)
{
    int idx = blockIdx.x*blockDim.x + threadIdx.x;
    if (idx >= Mm*Mm*Dd) return;
    int a = idx / (Mm*Dd);
    int b = (idx / Dd) % Mm;
    g_R[idx] = (b <= a) ? qs[idx] : 0.f;
}

// ---------------- 64x64 SGEMM (CAP=3: k from max(bm,bn)) ----------------
template<int TA, int TB, int CAP=0>
__global__ void sgemm(int M_, int N_, int K_,
                      const float* __restrict__ A, int lda,
                      const float* __restrict__ B, int ldb,
                      float* __restrict__ C, int ldc,
                      float alpha, float beta)
{
    const int BM = 64, BN = 64, BK = 16;
    __shared__ float As[BK][BM+1];
    __shared__ float Bs[BK][BN+1];
    int bm = blockIdx.y*BM, bn = blockIdx.x*BN;
    int tid = threadIdx.x;
    int tm = (tid/16)*4, tn = (tid%16)*4;
    int kstart = 0;
    if (CAP == 3) kstart = ((bm > bn ? bm : bn)/BK)*BK;
    float acc[4][4] = {};
    for (int k0 = kstart; k0 < K_; k0 += BK){
        if (!TA){
            for (int i = tid; i < BM*BK; i += 256){
                int kk = i%BK, mm = i/BK;
                int gm = bm+mm, gk = k0+kk;
                As[kk][mm] = (gm < M_ && gk < K_) ? A[(size_t)gm*lda + gk] : 0.f;
            }
        } else {
            for (int i = tid; i < BM*BK; i += 256){
                int mm = i%BM, kk = i/BM;
                int gm = bm+mm, gk = k0+kk;
                As[kk][mm] = (gm < M_ && gk < K_) ? A[(size_t)gk*lda + gm] : 0.f;
            }
        }
        if (!TB){
            for (int i = tid; i < BN*BK; i += 256){
                int nn = i%BN, kk = i/BN;
                int gn = bn+nn, gk = k0+kk;
                Bs[kk][nn] = (gn < N_ && gk < K_) ? B[(size_t)gk*ldb + gn] : 0.f;
            }
        } else {
            for (int i = tid; i < BN*BK; i += 256){
                int kk = i%BK, nn = i/BK;
                int gn = bn+nn, gk = k0+kk;
                Bs[kk][nn] = (gn < N_ && gk < K_) ? B[(size_t)gn*ldb + gk] : 0.f;
            }
        }
        __syncthreads();
        #pragma unroll
        for (int kk = 0; kk < BK; kk++){
            float ra[4], rb[4];
            #pragma unroll
            for (int i = 0; i < 4; i++){ ra[i] = As[kk][tm+i]; rb[i] = Bs[kk][tn+i]; }
            #pragma unroll
            for (int i = 0; i < 4; i++)
                #pragma unroll
                for (int j = 0; j < 4; j++)
                    acc[i][j] = fmaf(ra[i], rb[j], acc[i][j]);
        }
        __syncthreads();
    }
    #pragma unroll
    for (int i = 0; i < 4; i++){
        int gm = bm + tm + i;
        if (gm >= M_) continue;
        #pragma unroll
        for (int j = 0; j < 4; j++){
            int gn = bn + tn + j;
            if (gn >= N_) continue;
            float prev = (beta != 0.f) ? C[(size_t)gm*ldc + gn] : 0.f;
            C[(size_t)gm*ldc + gn] = alpha*acc[i][j] + beta*prev;
        }
    }
}

// ---------------- 128x128 SGEMM, 8x8/thread, split-K, caps ----------------
template<int TA, int TB, int CAP>
__global__ void sgemm128(int M_, int N_, int K_, int Kchunk,
                         const float* __restrict__ A, int lda,
                         const float* __restrict__ B, int ldb,
                         float* __restrict__ C, int ldc, size_t partStride)
{
    const int BM = 128, BN = 128, BK = 16;
    __shared__ float As[BK][BM+4];
    __shared__ float Bs[BK][BN+4];
    int bm = blockIdx.y*BM, bn = blockIdx.x*BN;
    int kbeg = blockIdx.z*Kchunk;
    int kend = kbeg + Kchunk; if (kend > K_) kend = K_;
    if (CAP == 1){
        int cap = ((bm < bn ? bm : bn) + BM)*Dd;
        if (kend > cap) kend = cap;
    }
    if (CAP == 2){
        int kb = (bn >> 5) & ~(BK-1);
        if (kbeg < kb) kbeg = kb;
    }
    float* Cb = C + (size_t)blockIdx.z*partStride;
    int tid = threadIdx.x;
    int tm = (tid/16)*8, tn = (tid%16)*8;
    float acc[8][8] = {};
    for (int k0 = kbeg; k0 < kend; k0 += BK){
        if (!TA){
            #pragma unroll
            for (int i = tid; i < BM*BK; i += 256){
                int kk = i%BK, mm = i/BK;
                As[kk][mm] = A[(size_t)(bm+mm)*lda + (k0+kk)];
            }
        } else {
            #pragma unroll
            for (int i = tid; i < BM*BK; i += 256){
                int mm = i%BM, kk = i/BM;
                As[kk][mm] = A[(size_t)(k0+kk)*lda + (bm+mm)];
            }
        }
        if (!TB){
            #pragma unroll
            for (int i = tid; i < BN*BK; i += 256){
                int nn = i%BN, kk = i/BN;
                Bs[kk][nn] = B[(size_t)(k0+kk)*ldb + (bn+nn)];
            }
        } else {
            #pragma unroll
            for (int i = tid; i < BN*BK; i += 256){
                int kk = i%BK, nn = i/BK;
                Bs[kk][nn] = B[(size_t)(bn+nn)*ldb + (k0+kk)];
            }
        }
        __syncthreads();
        #pragma unroll
        for (int kk = 0; kk < BK; kk++){
            float ra[8], rb[8];
            *(float4*)&ra[0] = *(const float4*)&As[kk][tm];
            *(float4*)&ra[4] = *(const float4*)&As[kk][tm+4];
            *(float4*)&rb[0] = *(const float4*)&Bs[kk][tn];
            *(float4*)&rb[4] = *(const float4*)&Bs[kk][tn+4];
            #pragma unroll
            for (int i = 0; i < 8; i++)
                #pragma unroll
                for (int j = 0; j < 8; j++)
                    acc[i][j] = fmaf(ra[i], rb[j], acc[i][j]);
        }
        __syncthreads();
    }
    #pragma unroll
    for (int i = 0; i < 8; i++){
        float* cp = Cb + (size_t)(bm+tm+i)*ldc + bn + tn;
        *(float4*)cp       = *(float4*)&acc[i][0];
        *(float4*)(cp + 4) = *(float4*)&acc[i][4];
    }
}

// ---------------- sum split-K partials ----------------
__global__ void reduce_parts_kernel(float* __restrict__ out,
                                    const float* __restrict__ parts,
                                    int S, int MN, int addBase)
{
    int idx = blockIdx.x*blockDim.x + threadIdx.x;
    if (idx >= MN) return;
    float s = addBase ? out[idx] : 0.f;
    for (int i = 0; i < S; i++) s += parts[(size_t)i*MN + idx];
    out[idx] = s;
}

// ---------------- batched SYRK for forward_var ----------------
__global__ void var_kernel(float* __restrict__ out_var, const float* __restrict__ beta_p)
{
    __shared__ __align__(16) float T[Mm*Dd];
    int n = blockIdx.x;
    int t = threadIdx.x;
    {
        const float4* src = (const float4*)(g_tmpF + (size_t)n*(Mm*Dd));
        float4* dst = (float4*)T;
        for (int i = t; i < (Mm*Dd)/4; i += 256) dst[i] = src[i];
    }
    __syncthreads();
    float invb = 1.f/beta_p[0];
    int e = t & 31, d0 = (t >> 5)*4;
    float a0=0.f, a1=0.f, a2=0.f, a3=0.f;
    #pragma unroll 4
    for (int m = 0; m < Mm; m++){
        float te = T[m*32 + e];
        float4 td = *(const float4*)&T[m*32 + d0];
        a0 = fmaf(td.x, te, a0);
        a1 = fmaf(td.y, te, a1);
        a2 = fmaf(td.z, te, a2);
        a3 = fmaf(td.w, te, a3);
    }
    float* vp = out_var + (size_t)n*Dd*Dd;
    vp[(d0+0)*32 + e] = a0 + ((d0+0)==e ? invb : 0.f);
    vp[(d0+1)*32 + e] = a1 + ((d0+1)==e ? invb : 0.f);
    vp[(d0+2)*32 + e] = a2 + ((d0+2)==e ? invb : 0.f);
    vp[(d0+3)*32 + e] = a3 + ((d0+3)==e ? invb : 0.f);
}

// ---------------- final scalar reduction -> lml ----------------
__global__ void reduce_lml_kernel(float* __restrict__ out_lml,
                                  const float* __restrict__ var_p,
                                  const float* __restrict__ beta_p,
                                  const float* __restrict__ qs)
{
    __shared__ double red[256];
    int t = threadIdx.x;
    double a1=0, a2=0, a3=0, a4=0, a5=0, a6=0;
    for (int i = t; i < Mm*Mm; i += 256){
        double kv = g_Kinv[i], uu = g_uuT[i];
        a1 += kv*(double)g_psi2[i];
        a2 += kv*uu;
        a3 += (double)g_KPK[i]*uu;
        a4 += (double)g_G[i]*uu;
    }
    for (int i = t; i < Mm; i += 256) a5 += log((double)g_Ldiag[i]);
    for (int i = t; i < Mm*Dd; i += 256){
        int mm = i/Dd, dd = i%Dd;
        double x = (double)qs[(size_t)mm*Mm*Dd + (size_t)mm*Dd + dd];
        a6 += log(x*x);
    }
    double sums[6] = {a1,a2,a3,a4,a5,a6};
    double res[6];
    for (int s = 0; s < 6; s++){
        red[t] = sums[s];
        __syncthreads();
        for (int w = 128; w > 0; w >>= 1){
            if (t < w) red[t] += red[t+w];
            __syncthreads();
        }
        res[s] = red[0];
        __syncthreads();
    }
    if (t == 0){
        double variance = var_p[0], beta = beta_p[0];
        double psi0 = (double)Nn*variance;
        double lml = -0.5*beta*(double)Dd*(psi0 - res[0]);
        double logdetK = 2.0*res[4];
        double kl = 0.5*(res[1] - (double)(Mm*Dd) + (double)Dd*logdetK - res[5]);
        lml -= kl;
        lml -= 0.5*beta*(res[2] - res[3]);
        out_lml[0] = (float)lml;
    }
}

// ---------------- host launcher ----------------
extern "C" void kernel_launch(void* const* d_in, const int* in_sizes, int n_in,
                              void* d_out, int out_size)
{
    const float* Xmean = (const float*)d_in[0];
    const float* Xvar  = (const float*)d_in[1];
    const float* Z     = (const float*)d_in[2];
    const float* qmu   = (const float*)d_in[3];
    const float* qs    = (const float*)d_in[4];
    const float* ls    = (const float*)d_in[5];
    const float* var_p = (const float*)d_in[6];
    const float* beta_p= (const float*)d_in[7];

    float* out      = (float*)d_out;
    float* out_mean = out;
    float* out_var  = out + Nn*Dd;
    float* out_lml  = out + Nn*Dd + (size_t)Nn*Dd*Dd;

    float *pPsi1, *pKinv, *pA1, *pR, *puuT, *puuTp, *pGp, *pP2, *pKPK, *pG, *pTmpF, *pPsi2, *pLinv;
    cudaGetSymbolAddress((void**)&pPsi1, g_psi1);
    cudaGetSymbolAddress((void**)&pKinv, g_Kinv);
    cudaGetSymbolAddress((void**)&pA1,   g_A1);
    cudaGetSymbolAddress((void**)&pR,    g_R);
    cudaGetSymbolAddress((void**)&puuT,  g_uuT);
    cudaGetSymbolAddress((void**)&puuTp, g_uuTp);
    cudaGetSymbolAddress((void**)&pGp,   g_Gp);
    cudaGetSymbolAddress((void**)&pP2,   g_P2);
    cudaGetSymbolAddress((void**)&pKPK,  g_KPK);
    cudaGetSymbolAddress((void**)&pG,    g_G);
    cudaGetSymbolAddress((void**)&pTmpF, g_tmpF);
    cudaGetSymbolAddress((void**)&pPsi2, g_psi2);
    cudaGetSymbolAddress((void**)&pLinv, g_Linv);

    const int CHOLINV_SMEM = (TRI + 8448)*4;   // 165376 B
    const int LVL2_SMEM = 3*4160*4;            // 49920 B
    cudaFuncSetAttribute(cholinv_kernel, cudaFuncAttributeMaxDynamicSharedMemorySize, CHOLINV_SMEM);
    cudaFuncSetAttribute(inv_lvl2_kernel, cudaFuncAttributeMaxDynamicSharedMemorySize, LVL2_SMEM);

    static cudaStream_t s1 = nullptr, s2 = nullptr;
    static cudaEvent_t eS = nullptr, eK = nullptr, eR = nullptr,
                       e1 = nullptr, e2 = nullptr, e3 = nullptr, e4 = nullptr;
    if (!s1){
        cudaStreamCreateWithFlags(&s1, cudaStreamNonBlocking);
        cudaStreamCreateWithFlags(&s2, cudaStreamNonBlocking);
        cudaEventCreateWithFlags(&eS, cudaEventDisableTiming);
        cudaEventCreateWithFlags(&eK, cudaEventDisableTiming);
        cudaEventCreateWithFlags(&eR, cudaEventDisableTiming);
        cudaEventCreateWithFlags(&e1, cudaEventDisableTiming);
        cudaEventCreateWithFlags(&e2, cudaEventDisableTiming);
        cudaEventCreateWithFlags(&e3, cudaEventDisableTiming);
        cudaEventCreateWithFlags(&e4, cudaEventDisableTiming);
    }

    // ---- fork point ----
    cudaEventRecord(eS, 0);

    // ---- branch s2: Kmm prep, maskR (eR), then uuT chain (e2) ----
    cudaStreamWaitEvent(s2, eS, 0);
    prep_kmm_kernel<<<(Mm*Mm+255)/256, 256, 0, s2>>>(Z, ls, var_p);
    cudaEventRecord(eK, s2);
    maskR_kernel<<<(Mm*Mm*Dd+255)/256, 256, 0, s2>>>(qs);
    cudaEventRecord(eR, s2);
    {
        dim3 g((Mm+63)/64, (Mm+63)/64);
        sgemm<0,1><<<g, 256, 0, s2>>>(Mm, Mm, Dd, qmu, Dd, qmu, Dd, puuT, Mm, 1.f, 0.f);
        dim3 g2(Mm/128, Mm/128, 32);
        sgemm128<0,1,1><<<g2, 256, 0, s2>>>(Mm, Mm, Mm*Dd, (Mm*Dd)/32, pR, Mm*Dd, pR, Mm*Dd,
                                            puuTp, Mm, (size_t)Mm*Mm);
        reduce_parts_kernel<<<(Mm*Mm+255)/256, 256, 0, s2>>>(puuT, puuTp, 32, Mm*Mm, 1);
    }
    cudaEventRecord(e2, s2);

    // ---- branch s1: Cholesky + inversion chain ----
    cudaStreamWaitEvent(s1, eK, 0);
    cholinv_kernel<<<1, 1024, CHOLINV_SMEM, s1>>>();
    inv_lvl2_kernel<<<2, 256, LVL2_SMEM, s1>>>();
    inv_lvl3a_kernel<<<4, 256, 0, s1>>>();
    inv_lvl3b_kernel<<<4, 256, 0, s1>>>();
    unpack_linv_kernel<<<(Mm*Mm+255)/256, 256, 0, s1>>>();
    {
        dim3 g((Mm+63)/64, (Mm+63)/64);
        sgemm<1,0,3><<<g, 256, 0, s1>>>(Mm, Mm, Mm, pLinv, Mm, pLinv, Mm, pKinv, Mm, 1.f, 0.f);
    }
    cudaEventRecord(e1, s1);

    // ---- origin: per-n prep + psi chain ----
    prep_n_kernel<<<(Nn+255)/256, 256>>>(Xmean, Xvar, ls);
    {
        dim3 b(32,8), g(Mm/32, Nn/8);
        e2psi1_kernel<<<g, b>>>(Z, var_p);
    }
    cudaStreamWaitEvent(0, eK, 0);   // psi2 needs qmk
    {
        dim3 b(16,16), g(136, 8);
        psi2_kernel<<<g, b>>>(Z);
        psi2_combine_kernel<<<(Mm*Mm+255)/256, 256>>>(var_p);
    }

    // ---- join Kinv, compute A1 ----
    cudaStreamWaitEvent(0, e1, 0);
    {
        dim3 g((Mm+63)/64, (Nn+63)/64);
        sgemm<0,0><<<g, 256>>>(Nn, Mm, Mm, pPsi1, Mm, pKinv, Mm, pA1, Mm, 1.f, 0.f);
    }
    cudaEventRecord(e3, 0);

    // ---- s1 post-A1: mean, P2, KPK, G ----
    cudaStreamWaitEvent(s1, e3, 0);
    {
        dim3 g((Dd+63)/64, (Nn+63)/64);
        sgemm<0,0><<<g, 256, 0, s1>>>(Nn, Dd, Mm, pA1, Mm, qmu, Dd, out_mean, Dd, 1.f, 0.f);
    }
    {
        dim3 g((Mm+63)/64, (Mm+63)/64);
        sgemm<0,0><<<g, 256, 0, s1>>>(Mm, Mm, Mm, pKinv, Mm, pPsi2, Mm, pP2, Mm, 1.f, 0.f);
        sgemm<0,0><<<g, 256, 0, s1>>>(Mm, Mm, Mm, pP2, Mm, pKinv, Mm, pKPK, Mm, 1.f, 0.f);
    }
    {
        dim3 g(Mm/128, Mm/128, 8);
        sgemm128<1,0,0><<<g, 256, 0, s1>>>(Mm, Mm, Nn, Nn/8, pA1, Mm, pA1, Mm,
                                           pGp, Mm, (size_t)Mm*Mm);
        reduce_parts_kernel<<<(Mm*Mm+255)/256, 256, 0, s1>>>(pG, pGp, 8, Mm*Mm, 0);
    }
    cudaEventRecord(e4, s1);

    // ---- origin: tmpF (needs only R) -> var ----
    cudaStreamWaitEvent(0, eR, 0);
    {
        dim3 g((Mm*Dd)/128, Nn/128, 1);
        sgemm128<0,0,2><<<g, 256>>>(Nn, Mm*Dd, Mm, Mm, pA1, Mm, pR, Mm*Dd,
                                    pTmpF, Mm*Dd, 0);
    }
    var_kernel<<<Nn, 256>>>(out_var, beta_p);

    // ---- final join: needs uuT (e2) and s1 chain (e4) ----
    cudaStreamWaitEvent(0, e2, 0);
    cudaStreamWaitEvent(0, e4, 0);
    reduce_lml_kernel<<<1, 256>>>(out_lml, var_p, beta_p, qs);
}

// round 9
// speedup vs baseline: 1.6678x; 1.6678x over previous
#include <cuda_runtime.h>
#include <cuda_bf16.h>
#include <math.h>

#define Nn 1024
#define Qq 32
#define Mm 256
#define Dd 32
#define JITTER 1e-6f
#define TRI (Mm*(Mm+1)/2)

__device__ __forceinline__ int off(int i){ return (i*(i+1))>>1; }

// ---------------- scratch ----------------
__device__ float g_hw1[Nn*Qq];
__device__ float g_wm1[Nn*Qq];
__device__ float g_hw2[Nn*Qq];
__device__ float g_w2[Nn*Qq];
__device__ float g_wm2[Nn*Qq];
__device__ float g_G1[Nn];
__device__ float g_F2[Nn];
__device__ float g_E2[Nn*Mm];
__device__ float g_qmk[Mm*Mm];
__device__ float g_Kmm[Mm*Mm];
__device__ float g_Lp[TRI];
__device__ float g_Ldiag[Mm];
__device__ float g_T128[128*128];
__device__ float g_Linv[Mm*Mm];
__device__ float g_Kinv[Mm*Mm];
__device__ float g_psi1[Nn*Mm];
__device__ float g_psi2[Mm*Mm];
__device__ float g_psi2p[8*Mm*Mm];
__device__ float g_A1[Nn*Mm];
__device__ float g_R[Mm*Mm*Dd];
__device__ float g_uuT[Mm*Mm];
__device__ float g_uuTp[16*Mm*Mm];
__device__ float g_Gp[8*Mm*Mm];
__device__ float g_P2[Mm*Mm];
__device__ float g_KPK[Mm*Mm];
__device__ float g_G[Mm*Mm];
__device__ float g_tmpF[(size_t)Nn*Mm*Dd];

// ---------------- per-n prep ----------------
__global__ void prep_n_kernel(const float* __restrict__ Xmean,
                              const float* __restrict__ Xvar,
                              const float* __restrict__ ls)
{
    int n = blockIdx.x*blockDim.x + threadIdx.x;
    if (n >= Nn) return;
    float ld1 = 0.f, ld2 = 0.f, a1 = 0.f, a2 = 0.f;
    #pragma unroll
    for (int q = 0; q < Qq; q++){
        float l = ls[q];
        float l2 = l*l;
        float S = Xvar[n*Qq+q];
        float mu = Xmean[n*Qq+q];
        float d1 = l2 + S;
        float d2 = l2 + 2.f*S;
        float w1 = 1.f/d1;
        float w2 = 1.f/d2;
        g_hw1[n*Qq+q] = 0.5f*w1;
        g_hw2[n*Qq+q] = 0.5f*w2;
        g_w2[n*Qq+q]  = w2;
        g_wm1[n*Qq+q] = w1*mu;
        g_wm2[n*Qq+q] = w2*mu;
        ld1 += logf(d1/l2);
        ld2 += logf(d2/l2);
        a1 = fmaf(w1*mu, mu, a1);
        a2 = fmaf(w2*mu, mu, a2);
    }
    g_G1[n] = -0.5f*ld1 - 0.5f*a1;
    g_F2[n] = -0.5f*ld2 - a2;
}

// ---------------- qmk and Kmm ----------------
__global__ void prep_kmm_kernel(const float* __restrict__ Z,
                                const float* __restrict__ ls,
                                const float* __restrict__ var_p)
{
    int idx = blockIdx.x*blockDim.x + threadIdx.x;
    if (idx >= Mm*Mm) return;
    int m = idx / Mm, k = idx % Mm;
    float s = 0.f;
    #pragma unroll
    for (int q = 0; q < Qq; q++){
        float l = ls[q];
        float d = Z[m*Qq+q] - Z[k*Qq+q];
        s += (d*d)/(l*l);
    }
    g_qmk[idx] = s;
    float v = var_p[0];
    g_Kmm[idx] = v*expf(-0.5f*s) + ((m==k)?JITTER:0.f);
}

// ---------------- fused E2 + psi1 ----------------
__global__ void e2psi1_kernel(const float* __restrict__ Z,
                              const float* __restrict__ var_p)
{
    int tx = threadIdx.x, ty = threadIdx.y;
    int m = blockIdx.x*32 + tx;
    int n0 = blockIdx.y*8;
    int n = n0 + ty;
    __shared__ float Zs[32][33];
    __shared__ float w1b[8][32], wm1b[8][32];
    __shared__ float w2b[8][32], wm2b[8][32], gs[8];
    int t = ty*32 + tx;
    for (int i = t; i < 32*Qq; i += 256){
        int r = i/Qq, q = i%Qq;
        Zs[r][q] = Z[(blockIdx.x*32+r)*Qq + q];
    }
    for (int i = t; i < 8*Qq; i += 256){
        int r = i/Qq, q = i%Qq;
        w1b[r][q]  = g_hw1[(n0+r)*Qq + q];
        wm1b[r][q] = g_wm1[(n0+r)*Qq + q];
        w2b[r][q]  = g_w2[(n0+r)*Qq + q];
        wm2b[r][q] = g_wm2[(n0+r)*Qq + q];
    }
    if (t < 8) gs[t] = g_G1[n0+t];
    __syncthreads();
    float s1 = 0.f, s2 = 0.f;
    #pragma unroll
    for (int q = 0; q < Qq; q++){
        float z = Zs[tx][q];
        float t1 = fmaf(-w1b[ty][q], z, wm1b[ty][q]);
        s1 = fmaf(t1, z, s1);
        float t2 = fmaf(-0.25f*w2b[ty][q], z, wm2b[ty][q]);
        s2 = fmaf(t2, z, s2);
    }
    g_psi1[n*Mm + m] = var_p[0]*__expf(gs[ty] + s1);
    g_E2[n*Mm + m] = s2;
}

// ---------------- psi2 ----------------
__global__ void psi2_kernel(const float* __restrict__ Z)
{
    int rem = blockIdx.x, bi = 0;
    for (bi = 0; bi < 16; bi++){ int len = 16-bi; if (rem < len) break; rem -= len; }
    int bj = bi + rem;
    int chunk = blockIdx.y;
    int tx = threadIdx.x, ty = threadIdx.y;
    int m = bi*16 + ty;
    int k = bj*16 + tx;
    int t = ty*16 + tx;

    __shared__ float Zm[16][33], Zk[16][33];
    for (int i = t; i < 16*Qq; i += 256){
        int r = i/Qq, q = i%Qq;
        Zm[r][q] = Z[(bi*16+r)*Qq + q];
        Zk[r][q] = Z[(bj*16+r)*Qq + q];
    }
    __syncthreads();
    float zp[Qq];
    #pragma unroll
    for (int q = 0; q < Qq; q++) zp[q] = Zm[ty][q]*Zk[tx][q];
    float base = -0.25f*g_qmk[m*Mm + k];

    __shared__ float wb[16][33], F2s[16];
    __shared__ float Em[16][17], Ek[16][17];
    float acc = 0.f;
    int nbeg = chunk*(Nn/8), nend = nbeg + Nn/8;
    for (int n0 = nbeg; n0 < nend; n0 += 16){
        __syncthreads();
        for (int i = t; i < 16*Qq; i += 256){
            int r = i/Qq, q = i%Qq;
            wb[r][q] = g_hw2[(n0+r)*Qq + q];
        }
        {
            int nn = t >> 4, r = t & 15;
            Em[nn][r] = g_E2[(n0+nn)*Mm + bi*16 + r];
            Ek[nn][r] = g_E2[(n0+nn)*Mm + bj*16 + r];
        }
        if (t < 16) F2s[t] = g_F2[n0+t];
        __syncthreads();
        #pragma unroll 2
        for (int nn = 0; nn < 16; nn++){
            float dot = 0.f;
            #pragma unroll
            for (int q = 0; q < Qq; q++)
                dot = fmaf(wb[nn][q], zp[q], dot);
            float e = base + F2s[nn] + Em[nn][ty] + Ek[nn][tx] - dot;
            acc += __expf(e);
        }
    }
    g_psi2p[chunk*(Mm*Mm) + m*Mm + k] = acc;
}

__global__ void psi2_combine_kernel(const float* __restrict__ var_p)
{
    int idx = blockIdx.x*blockDim.x + threadIdx.x;
    if (idx >= Mm*Mm) return;
    int m = idx / Mm, k = idx % Mm;
    int src = ((m>>4) <= (k>>4)) ? (m*Mm + k) : (k*Mm + m);
    float s = 0.f;
    #pragma unroll
    for (int c = 0; c < 8; c++) s += g_psi2p[c*(Mm*Mm) + src];
    float v = var_p[0];
    g_psi2[idx] = v*v*s;
}

// ============ Cholesky (1024 thr, R5 version) + diag inversion + level-1 ============
__global__ void cholinv_kernel()
{
    extern __shared__ float sm[];
    float* sL = sm;            // TRI
    float* Vt = sm + TRI;      // 8448
    __shared__ float col1[Mm], col2[Mm];
    int t = threadIdx.x;
    int warp = t >> 5, lane = t & 31;

    for (int idx = t; idx < TRI; idx += 1024){
        int i = (int)((sqrtf(8.f*(float)idx + 1.f) - 1.f)*0.5f);
        while (off(i+1) <= idx) i++;
        while (off(i) > idx) i--;
        int j = idx - off(i);
        sL[idx] = g_Kmm[i*Mm + j];
    }
    __syncthreads();

    for (int k = 0; k < Mm; k += 2){
        if (t == 0) sL[off(k)+k] = sqrtf(sL[off(k)+k]);
        __syncthreads();
        float invk = 1.f/sL[off(k)+k];
        float v1 = 0.f;
        if (t > k && t < Mm){ v1 = sL[off(t)+k]*invk; sL[off(t)+k] = v1; }
        if (t < Mm) col1[t] = v1;
        __syncthreads();
        float tmp = 0.f;
        if (t >= k+1 && t < Mm) tmp = sL[off(t)+(k+1)] - col1[t]*col1[k+1];
        if (t == k+1) sL[off(k+1)+(k+1)] = sqrtf(tmp);
        __syncthreads();
        float inv2 = 1.f/sL[off(k+1)+(k+1)];
        float v2 = 0.f;
        if (t > k+1 && t < Mm){ v2 = tmp*inv2; sL[off(t)+(k+1)] = v2; }
        if (t < Mm) col2[t] = v2;
        __syncthreads();
        for (int i = k+2+warp; i < Mm; i += 32){
            float ci1 = col1[i], ci2 = col2[i];
            int b = off(i);
            for (int j = k+2+lane; j <= i; j += 32)
                sL[b+j] -= ci1*col1[j] + ci2*col2[j];
        }
        __syncthreads();
    }
    if (t < Mm) g_Ldiag[t] = sL[off(t)+t];
    __syncthreads();

    if (warp < 8){
        int r0 = warp*32;
        float* V = Vt + warp*1056;
        int c = lane;
        for (int r = 0; r < 32; r++){
            float sum = 0.f;
            for (int k = c; k < r; k++)
                sum = fmaf(sL[off(r0+r)+r0+k], V[k*33+c], sum);
            float diag = sL[off(r0+r)+r0+r];
            float v;
            if (c < r)       v = -sum/diag;
            else if (c == r) v = 1.f/diag;
            else             v = 0.f;
            V[r*33+c] = v;
        }
    }
    __syncthreads();
    {
        int pos = t & 1023;
        int r = pos >> 5, c = pos & 31;
        for (int b = 0; b < 8; b++)
            if (c <= r) sL[off(b*32+r)+b*32+c] = Vt[b*1056 + r*33 + c];
    }
    __syncthreads();

    // level-1 combine: 4 pairs concurrently
    {
        int p  = t >> 8;
        int ti = t & 255;
        int i  = ti >> 3;
        int j0 = (ti & 7)*4;
        int row0 = p*64;
        float acc[4] = {0,0,0,0};
        for (int k = 0; k < 32; k++){
            float b = sL[off(row0+32+i)+row0+k];
            #pragma unroll
            for (int jj = 0; jj < 4; jj++){
                int j = j0+jj;
                if (j <= k) acc[jj] = fmaf(b, sL[off(row0+k)+row0+j], acc[jj]);
            }
        }
        float* Tp = Vt + p*1056;
        #pragma unroll
        for (int jj = 0; jj < 4; jj++) Tp[i*33 + j0+jj] = acc[jj];
        __syncthreads();
        float acc2[4] = {0,0,0,0};
        for (int k = 0; k <= i; k++){
            float cv = sL[off(row0+32+i)+row0+32+k];
            #pragma unroll
            for (int jj = 0; jj < 4; jj++)
                acc2[jj] = fmaf(cv, Tp[k*33 + j0+jj], acc2[jj]);
        }
        #pragma unroll
        for (int jj = 0; jj < 4; jj++)
            sL[off(row0+32+i)+row0+j0+jj] = -acc2[jj];
    }
    __syncthreads();

    for (int idx = t; idx < TRI; idx += 1024) g_Lp[idx] = sL[idx];
}

// ============ level-2 combine (64->128), smem-staged, 2 CTAs ============
__global__ void inv_lvl2_kernel()
{
    extern __shared__ float sm[];
    float* sA = sm;             // 64*65
    float* sB = sm + 4160;      // 64*65
    float* sT = sm + 8320;      // 64*65
    int row0 = blockIdx.x*128;
    int t = threadIdx.x;
    int lr = t >> 2, q = (t & 3)*16;
    for (int c = 0; c < 16; c++){
        int col = q + c;
        sB[lr*65 + col] = g_Lp[off(row0+64+lr) + row0 + col];
        sA[lr*65 + col] = (col <= lr) ? g_Lp[off(row0+lr) + row0 + col] : 0.f;
    }
    __syncthreads();
    int i0 = (t >> 4)*4, j0 = (t & 15)*4;
    float acc[4][4] = {};
    for (int k = 0; k < 64; k++){
        float b[4], a[4];
        #pragma unroll
        for (int ii = 0; ii < 4; ii++) b[ii] = sB[(i0+ii)*65 + k];
        #pragma unroll
        for (int jj = 0; jj < 4; jj++) a[jj] = sA[k*65 + j0+jj];
        #pragma unroll
        for (int ii = 0; ii < 4; ii++)
            #pragma unroll
            for (int jj = 0; jj < 4; jj++)
                acc[ii][jj] = fmaf(b[ii], a[jj], acc[ii][jj]);
    }
    #pragma unroll
    for (int ii = 0; ii < 4; ii++)
        #pragma unroll
        for (int jj = 0; jj < 4; jj++)
            sT[(i0+ii)*65 + j0+jj] = acc[ii][jj];
    __syncthreads();
    for (int c = 0; c < 16; c++){
        int col = q + c;
        sB[lr*65 + col] = (col <= lr) ? g_Lp[off(row0+64+lr) + row0+64 + col] : 0.f;
    }
    __syncthreads();
    float acc2[4][4] = {};
    for (int k = 0; k < 64; k++){
        float cv[4], tv[4];
        #pragma unroll
        for (int ii = 0; ii < 4; ii++) cv[ii] = sB[(i0+ii)*65 + k];
        #pragma unroll
        for (int jj = 0; jj < 4; jj++) tv[jj] = sT[k*65 + j0+jj];
        #pragma unroll
        for (int ii = 0; ii < 4; ii++)
            #pragma unroll
            for (int jj = 0; jj < 4; jj++)
                acc2[ii][jj] = fmaf(cv[ii], tv[jj], acc2[ii][jj]);
    }
    #pragma unroll
    for (int ii = 0; ii < 4; ii++)
        #pragma unroll
        for (int jj = 0; jj < 4; jj++)
            g_Lp[off(row0+64+i0+ii)+row0+j0+jj] = -acc2[ii][jj];
}

// ============ level-3a: T128 = B * Ainv(128), smem-staged, 4 CTAs ============
__global__ void inv_lvl3a_kernel()
{
    __shared__ float sB[64*33];
    __shared__ float sA[32*65];
    int bi = (blockIdx.x >> 1)*64, bj = (blockIdx.x & 1)*64;
    int t = threadIdx.x;
    int i0 = (t >> 4)*4, j0 = (t & 15)*4;
    float acc[4][4] = {};
    for (int kc = 0; kc < 128; kc += 32){
        __syncthreads();
        {
            int lr = t >> 2, q = (t & 3)*8;
            for (int c = 0; c < 8; c++)
                sB[lr*33 + q + c] = g_Lp[off(128 + bi + lr) + kc + q + c];
            int kr = t >> 3, q2 = (t & 7)*8;
            for (int c = 0; c < 8; c++){
                int j = bj + q2 + c;
                sA[kr*65 + q2 + c] = (j <= kc+kr) ? g_Lp[off(kc+kr) + j] : 0.f;
            }
        }
        __syncthreads();
        #pragma unroll
        for (int k = 0; k < 32; k++){
            float b[4], a[4];
            #pragma unroll
            for (int ii = 0; ii < 4; ii++) b[ii] = sB[(i0+ii)*33 + k];
            #pragma unroll
            for (int jj = 0; jj < 4; jj++) a[jj] = sA[k*65 + j0+jj];
            #pragma unroll
            for (int ii = 0; ii < 4; ii++)
                #pragma unroll
                for (int jj = 0; jj < 4; jj++)
                    acc[ii][jj] = fmaf(b[ii], a[jj], acc[ii][jj]);
        }
    }
    #pragma unroll
    for (int ii = 0; ii < 4; ii++)
        #pragma unroll
        for (int jj = 0; jj < 4; jj++)
            g_T128[(bi+i0+ii)*128 + bj+j0+jj] = acc[ii][jj];
}

// ============ level-3b: O = -Cinv(128) * T128, smem-staged, 4 CTAs ============
__global__ void inv_lvl3b_kernel()
{
    __shared__ float sC[64*33];
    __shared__ float sT[32*65];
    int bi = (blockIdx.x >> 1)*64, bj = (blockIdx.x & 1)*64;
    int t = threadIdx.x;
    int i0 = (t >> 4)*4, j0 = (t & 15)*4;
    float acc[4][4] = {};
    for (int kc = 0; kc < 128; kc += 32){
        __syncthreads();
        {
            int lr = t >> 2, q = (t & 3)*8;
            for (int c = 0; c < 8; c++){
                int k = kc + q + c;
                sC[lr*33 + q + c] = (k <= bi+lr) ? g_Lp[off(128 + bi + lr) + 128 + k] : 0.f;
            }
            int kr = t >> 3, q2 = (t & 7)*8;
            for (int c = 0; c < 8; c++)
                sT[kr*65 + q2 + c] = g_T128[(kc+kr)*128 + bj + q2 + c];
        }
        __syncthreads();
        #pragma unroll
        for (int k = 0; k < 32; k++){
            float cv[4], tv[4];
            #pragma unroll
            for (int ii = 0; ii < 4; ii++) cv[ii] = sC[(i0+ii)*33 + k];
            #pragma unroll
            for (int jj = 0; jj < 4; jj++) tv[jj] = sT[k*65 + j0+jj];
            #pragma unroll
            for (int ii = 0; ii < 4; ii++)
                #pragma unroll
                for (int jj = 0; jj < 4; jj++)
                    acc[ii][jj] = fmaf(cv[ii], tv[jj], acc[ii][jj]);
        }
    }
    #pragma unroll
    for (int ii = 0; ii < 4; ii++)
        #pragma unroll
        for (int jj = 0; jj < 4; jj++)
            g_Lp[off(128+bi+i0+ii) + bj+j0+jj] = -acc[ii][jj];
}

__global__ void unpack_linv_kernel()
{
    int idx = blockIdx.x*blockDim.x + threadIdx.x;
    if (idx >= Mm*Mm) return;
    int i = idx / Mm, j = idx % Mm;
    g_Linv[idx] = (j <= i) ? g_Lp[off(i)+j] : 0.f;
}

// ---------------- masked R ----------------
__global__ void maskR_kernel(const float* __restrict__ qs)
{
    int idx = blockIdx.x*blockDim.x + threadIdx.x;
    if (idx >= Mm*Mm*Dd) return;
    int a = idx / (Mm*Dd);
    int b = (idx / Dd) % Mm;
    g_R[idx] = (b <= a) ? qs[idx] : 0.f;
}

// ---------------- 64x64 SGEMM (CAP=3: k from max(bm,bn)) ----------------
template<int TA, int TB, int CAP=0>
__global__ void sgemm(int M_, int N_, int K_,
                      const float* __restrict__ A, int lda,
                      const float* __restrict__ B, int ldb,
                      float* __restrict__ C, int ldc,
                      float alpha, float beta)
{
    const int BM = 64, BN = 64, BK = 16;
    __shared__ float As[BK][BM+1];
    __shared__ float Bs[BK][BN+1];
    int bm = blockIdx.y*BM, bn = blockIdx.x*BN;
    int tid = threadIdx.x;
    int tm = (tid/16)*4, tn = (tid%16)*4;
    int kstart = 0;
    if (CAP == 3) kstart = ((bm > bn ? bm : bn)/BK)*BK;
    float acc[4][4] = {};
    for (int k0 = kstart; k0 < K_; k0 += BK){
        if (!TA){
            for (int i = tid; i < BM*BK; i += 256){
                int kk = i%BK, mm = i/BK;
                int gm = bm+mm, gk = k0+kk;
                As[kk][mm] = (gm < M_ && gk < K_) ? A[(size_t)gm*lda + gk] : 0.f;
            }
        } else {
            for (int i = tid; i < BM*BK; i += 256){
                int mm = i%BM, kk = i/BM;
                int gm = bm+mm, gk = k0+kk;
                As[kk][mm] = (gm < M_ && gk < K_) ? A[(size_t)gk*lda + gm] : 0.f;
            }
        }
        if (!TB){
            for (int i = tid; i < BN*BK; i += 256){
                int nn = i%BN, kk = i/BN;
                int gn = bn+nn, gk = k0+kk;
                Bs[kk][nn] = (gn < N_ && gk < K_) ? B[(size_t)gk*ldb + gn] : 0.f;
            }
        } else {
            for (int i = tid; i < BN*BK; i += 256){
                int kk = i%BK, nn = i/BK;
                int gn = bn+nn, gk = k0+kk;
                Bs[kk][nn] = (gn < N_ && gk < K_) ? B[(size_t)gn*ldb + gk] : 0.f;
            }
        }
        __syncthreads();
        #pragma unroll
        for (int kk = 0; kk < BK; kk++){
            float ra[4], rb[4];
            #pragma unroll
            for (int i = 0; i < 4; i++){ ra[i] = As[kk][tm+i]; rb[i] = Bs[kk][tn+i]; }
            #pragma unroll
            for (int i = 0; i < 4; i++)
                #pragma unroll
                for (int j = 0; j < 4; j++)
                    acc[i][j] = fmaf(ra[i], rb[j], acc[i][j]);
        }
        __syncthreads();
    }
    #pragma unroll
    for (int i = 0; i < 4; i++){
        int gm = bm + tm + i;
        if (gm >= M_) continue;
        #pragma unroll
        for (int j = 0; j < 4; j++){
            int gn = bn + tn + j;
            if (gn >= N_) continue;
            float prev = (beta != 0.f) ? C[(size_t)gm*ldc + gn] : 0.f;
            C[(size_t)gm*ldc + gn] = alpha*acc[i][j] + beta*prev;
        }
    }
}

// ---------------- 128x128 SGEMM, 8x8/thread, split-K, caps ----------------
template<int TA, int TB, int CAP>
__global__ void sgemm128(int M_, int N_, int K_, int Kchunk,
                         const float* __restrict__ A, int lda,
                         const float* __restrict__ B, int ldb,
                         float* __restrict__ C, int ldc, size_t partStride)
{
    const int BM = 128, BN = 128, BK = 16;
    __shared__ float As[BK][BM+4];
    __shared__ float Bs[BK][BN+4];
    int bm = blockIdx.y*BM, bn = blockIdx.x*BN;
    int kbeg = blockIdx.z*Kchunk;
    int kend = kbeg + Kchunk; if (kend > K_) kend = K_;
    if (CAP == 1){
        int cap = ((bm < bn ? bm : bn) + BM)*Dd;
        if (kend > cap) kend = cap;
    }
    if (CAP == 2){
        int kb = (bn >> 5) & ~(BK-1);
        if (kbeg < kb) kbeg = kb;
    }
    float* Cb = C + (size_t)blockIdx.z*partStride;
    int tid = threadIdx.x;
    int tm = (tid/16)*8, tn = (tid%16)*8;
    float acc[8][8] = {};
    for (int k0 = kbeg; k0 < kend; k0 += BK){
        if (!TA){
            #pragma unroll
            for (int i = tid; i < BM*BK; i += 256){
                int kk = i%BK, mm = i/BK;
                As[kk][mm] = A[(size_t)(bm+mm)*lda + (k0+kk)];
            }
        } else {
            #pragma unroll
            for (int i = tid; i < BM*BK; i += 256){
                int mm = i%BM, kk = i/BM;
                As[kk][mm] = A[(size_t)(k0+kk)*lda + (bm+mm)];
            }
        }
        if (!TB){
            #pragma unroll
            for (int i = tid; i < BN*BK; i += 256){
                int nn = i%BN, kk = i/BN;
                Bs[kk][nn] = B[(size_t)(k0+kk)*ldb + (bn+nn)];
            }
        } else {
            #pragma unroll
            for (int i = tid; i < BN*BK; i += 256){
                int kk = i%BK, nn = i/BK;
                Bs[kk][nn] = B[(size_t)(bn+nn)*ldb + (k0+kk)];
            }
        }
        __syncthreads();
        #pragma unroll
        for (int kk = 0; kk < BK; kk++){
            float ra[8], rb[8];
            *(float4*)&ra[0] = *(const float4*)&As[kk][tm];
            *(float4*)&ra[4] = *(const float4*)&As[kk][tm+4];
            *(float4*)&rb[0] = *(const float4*)&Bs[kk][tn];
            *(float4*)&rb[4] = *(const float4*)&Bs[kk][tn+4];
            #pragma unroll
            for (int i = 0; i < 8; i++)
                #pragma unroll
                for (int j = 0; j < 8; j++)
                    acc[i][j] = fmaf(ra[i], rb[j], acc[i][j]);
        }
        __syncthreads();
    }
    #pragma unroll
    for (int i = 0; i < 8; i++){
        float* cp = Cb + (size_t)(bm+tm+i)*ldc + bn + tn;
        *(float4*)cp       = *(float4*)&acc[i][0];
        *(float4*)(cp + 4) = *(float4*)&acc[i][4];
    }
}

// ---------------- sum split-K partials ----------------
__global__ void reduce_parts_kernel(float* __restrict__ out,
                                    const float* __restrict__ parts,
                                    int S, int MN, int addBase)
{
    int idx = blockIdx.x*blockDim.x + threadIdx.x;
    if (idx >= MN) return;
    float s = addBase ? out[idx] : 0.f;
    for (int i = 0; i < S; i++) s += parts[(size_t)i*MN + idx];
    out[idx] = s;
}

// ---------------- batched SYRK for forward_var (float4) ----------------
__global__ void var_kernel(float* __restrict__ out_var, const float* __restrict__ beta_p)
{
    __shared__ __align__(16) float T[Mm*Dd];
    int n = blockIdx.x;
    int t = threadIdx.x;
    {
        const float4* src = (const float4*)(g_tmpF + (size_t)n*(Mm*Dd));
        float4* dst = (float4*)T;
        for (int i = t; i < (Mm*Dd)/4; i += 256) dst[i] = src[i];
    }
    __syncthreads();
    float invb = 1.f/beta_p[0];
    int e = t & 31, d0 = (t >> 5)*4;
    float a0=0.f, a1=0.f, a2=0.f, a3=0.f;
    #pragma unroll 4
    for (int m = 0; m < Mm; m++){
        float te = T[m*32 + e];
        float4 td = *(const float4*)&T[m*32 + d0];
        a0 = fmaf(td.x, te, a0);
        a1 = fmaf(td.y, te, a1);
        a2 = fmaf(td.z, te, a2);
        a3 = fmaf(td.w, te, a3);
    }
    float* vp = out_var + (size_t)n*Dd*Dd;
    vp[(d0+0)*32 + e] = a0 + ((d0+0)==e ? invb : 0.f);
    vp[(d0+1)*32 + e] = a1 + ((d0+1)==e ? invb : 0.f);
    vp[(d0+2)*32 + e] = a2 + ((d0+2)==e ? invb : 0.f);
    vp[(d0+3)*32 + e] = a3 + ((d0+3)==e ? invb : 0.f);
}

// ---------------- final scalar reduction -> lml ----------------
__global__ void reduce_lml_kernel(float* __restrict__ out_lml,
                                  const float* __restrict__ var_p,
                                  const float* __restrict__ beta_p,
                                  const float* __restrict__ qs)
{
    __shared__ double red[256];
    int t = threadIdx.x;
    double a1=0, a2=0, a3=0, a4=0, a5=0, a6=0;
    for (int i = t; i < Mm*Mm; i += 256){
        double kv = g_Kinv[i], uu = g_uuT[i];
        a1 += kv*(double)g_psi2[i];
        a2 += kv*uu;
        a3 += (double)g_KPK[i]*uu;
        a4 += (double)g_G[i]*uu;
    }
    for (int i = t; i < Mm; i += 256) a5 += log((double)g_Ldiag[i]);
    for (int i = t; i < Mm*Dd; i += 256){
        int mm = i/Dd, dd = i%Dd;
        double x = (double)qs[(size_t)mm*Mm*Dd + (size_t)mm*Dd + dd];
        a6 += log(x*x);
    }
    double sums[6] = {a1,a2,a3,a4,a5,a6};
    double res[6];
    for (int s = 0; s < 6; s++){
        red[t] = sums[s];
        __syncthreads();
        for (int w = 128; w > 0; w >>= 1){
            if (t < w) red[t] += red[t+w];
            __syncthreads();
        }
        res[s] = red[0];
        __syncthreads();
    }
    if (t == 0){
        double variance = var_p[0], beta = beta_p[0];
        double psi0 = (double)Nn*variance;
        double lml = -0.5*beta*(double)Dd*(psi0 - res[0]);
        double logdetK = 2.0*res[4];
        double kl = 0.5*(res[1] - (double)(Mm*Dd) + (double)Dd*logdetK - res[5]);
        lml -= kl;
        lml -= 0.5*beta*(res[2] - res[3]);
        out_lml[0] = (float)lml;
    }
}

// ---------------- host launcher (exact R5 topology) ----------------
extern "C" void kernel_launch(void* const* d_in, const int* in_sizes, int n_in,
                              void* d_out, int out_size)
{
    const float* Xmean = (const float*)d_in[0];
    const float* Xvar  = (const float*)d_in[1];
    const float* Z     = (const float*)d_in[2];
    const float* qmu   = (const float*)d_in[3];
    const float* qs    = (const float*)d_in[4];
    const float* ls    = (const float*)d_in[5];
    const float* var_p = (const float*)d_in[6];
    const float* beta_p= (const float*)d_in[7];

    float* out      = (float*)d_out;
    float* out_mean = out;
    float* out_var  = out + Nn*Dd;
    float* out_lml  = out + Nn*Dd + (size_t)Nn*Dd*Dd;

    float *pPsi1, *pKinv, *pA1, *pR, *puuT, *puuTp, *pGp, *pP2, *pKPK, *pG, *pTmpF, *pPsi2, *pLinv;
    cudaGetSymbolAddress((void**)&pPsi1, g_psi1);
    cudaGetSymbolAddress((void**)&pKinv, g_Kinv);
    cudaGetSymbolAddress((void**)&pA1,   g_A1);
    cudaGetSymbolAddress((void**)&pR,    g_R);
    cudaGetSymbolAddress((void**)&puuT,  g_uuT);
    cudaGetSymbolAddress((void**)&puuTp, g_uuTp);
    cudaGetSymbolAddress((void**)&pGp,   g_Gp);
    cudaGetSymbolAddress((void**)&pP2,   g_P2);
    cudaGetSymbolAddress((void**)&pKPK,  g_KPK);
    cudaGetSymbolAddress((void**)&pG,    g_G);
    cudaGetSymbolAddress((void**)&pTmpF, g_tmpF);
    cudaGetSymbolAddress((void**)&pPsi2, g_psi2);
    cudaGetSymbolAddress((void**)&pLinv, g_Linv);

    const int CHOLINV_SMEM = (TRI + 8448)*4;   // 165376 B
    const int LVL2_SMEM = 3*4160*4;            // 49920 B
    cudaFuncSetAttribute(cholinv_kernel, cudaFuncAttributeMaxDynamicSharedMemorySize, CHOLINV_SMEM);
    cudaFuncSetAttribute(inv_lvl2_kernel, cudaFuncAttributeMaxDynamicSharedMemorySize, LVL2_SMEM);

    static cudaStream_t s1 = nullptr, s2 = nullptr;
    static cudaEvent_t e0 = nullptr, e1 = nullptr, e2 = nullptr, e3 = nullptr, e4 = nullptr;
    if (!s1){
        cudaStreamCreateWithFlags(&s1, cudaStreamNonBlocking);
        cudaStreamCreateWithFlags(&s2, cudaStreamNonBlocking);
        cudaEventCreateWithFlags(&e0, cudaEventDisableTiming);
        cudaEventCreateWithFlags(&e1, cudaEventDisableTiming);
        cudaEventCreateWithFlags(&e2, cudaEventDisableTiming);
        cudaEventCreateWithFlags(&e3, cudaEventDisableTiming);
        cudaEventCreateWithFlags(&e4, cudaEventDisableTiming);
    }

    // ---- common prep on origin ----
    prep_n_kernel<<<(Nn+255)/256, 256>>>(Xmean, Xvar, ls);
    prep_kmm_kernel<<<(Mm*Mm+255)/256, 256>>>(Z, ls, var_p);
    cudaEventRecord(e0, 0);

    // ---- branch s1: Cholesky + block inversion chain ----
    cudaStreamWaitEvent(s1, e0, 0);
    cholinv_kernel<<<1, 1024, CHOLINV_SMEM, s1>>>();
    inv_lvl2_kernel<<<2, 256, LVL2_SMEM, s1>>>();
    inv_lvl3a_kernel<<<4, 256, 0, s1>>>();
    inv_lvl3b_kernel<<<4, 256, 0, s1>>>();
    unpack_linv_kernel<<<(Mm*Mm+255)/256, 256, 0, s1>>>();
    {
        dim3 g((Mm+63)/64, (Mm+63)/64);
        sgemm<1,0,3><<<g, 256, 0, s1>>>(Mm, Mm, Mm, pLinv, Mm, pLinv, Mm, pKinv, Mm, 1.f, 0.f);
    }
    cudaEventRecord(e1, s1);

    // ---- branch s2: R / uuT chain ----
    cudaStreamWaitEvent(s2, e0, 0);
    maskR_kernel<<<(Mm*Mm*Dd+255)/256, 256, 0, s2>>>(qs);
    {
        dim3 g((Mm+63)/64, (Mm+63)/64);
        sgemm<0,1><<<g, 256, 0, s2>>>(Mm, Mm, Dd, qmu, Dd, qmu, Dd, puuT, Mm, 1.f, 0.f);
        dim3 g2(Mm/128, Mm/128, 16);
        sgemm128<0,1,1><<<g2, 256, 0, s2>>>(Mm, Mm, Mm*Dd, (Mm*Dd)/16, pR, Mm*Dd, pR, Mm*Dd,
                                            puuTp, Mm, (size_t)Mm*Mm);
        reduce_parts_kernel<<<(Mm*Mm+255)/256, 256, 0, s2>>>(puuT, puuTp, 16, Mm*Mm, 1);
    }
    cudaEventRecord(e2, s2);

    // ---- origin: psi chain ----
    {
        dim3 b(32,8), g(Mm/32, Nn/8);
        e2psi1_kernel<<<g, b>>>(Z, var_p);
    }
    {
        dim3 b(16,16), g(136, 8);
        psi2_kernel<<<g, b>>>(Z);
        psi2_combine_kernel<<<(Mm*Mm+255)/256, 256>>>(var_p);
    }

    // ---- join Kinv, compute A1 ----
    cudaStreamWaitEvent(0, e1, 0);
    {
        dim3 g((Mm+63)/64, (Nn+63)/64);
        sgemm<0,0><<<g, 256>>>(Nn, Mm, Mm, pPsi1, Mm, pKinv, Mm, pA1, Mm, 1.f, 0.f);
    }
    cudaEventRecord(e3, 0);

    // ---- s1 post-A1: mean, P2, KPK, G ----
    cudaStreamWaitEvent(s1, e3, 0);
    {
        dim3 g((Dd+63)/64, (Nn+63)/64);
        sgemm<0,0><<<g, 256, 0, s1>>>(Nn, Dd, Mm, pA1, Mm, qmu, Dd, out_mean, Dd, 1.f, 0.f);
    }
    {
        dim3 g((Mm+63)/64, (Mm+63)/64);
        sgemm<0,0><<<g, 256, 0, s1>>>(Mm, Mm, Mm, pKinv, Mm, pPsi2, Mm, pP2, Mm, 1.f, 0.f);
        sgemm<0,0><<<g, 256, 0, s1>>>(Mm, Mm, Mm, pP2, Mm, pKinv, Mm, pKPK, Mm, 1.f, 0.f);
    }
    {
        dim3 g(Mm/128, Mm/128, 8);
        sgemm128<1,0,0><<<g, 256, 0, s1>>>(Mm, Mm, Nn, Nn/8, pA1, Mm, pA1, Mm,
                                           pGp, Mm, (size_t)Mm*Mm);
        reduce_parts_kernel<<<(Mm*Mm+255)/256, 256, 0, s1>>>(pG, pGp, 8, Mm*Mm, 0);
    }
    cudaEventRecord(e4, s1);

    // ---- origin: tmpF -> var ----
    cudaStreamWaitEvent(0, e2, 0);
    {
        dim3 g((Mm*Dd)/128, Nn/128, 1);
        sgemm128<0,0,2><<<g, 256>>>(Nn, Mm*Dd, Mm, Mm, pA1, Mm, pR, Mm*Dd,
                                    pTmpF, Mm*Dd, 0);
    }
    var_kernel<<<Nn, 256>>>(out_var, beta_p);

    // ---- final join ----
    cudaStreamWaitEvent(0, e4, 0);
    reduce_lml_kernel<<<1, 256>>>(out_lml, var_p, beta_p, qs);
}

// round 10
// speedup vs baseline: 1.7486x; 1.0484x over previous
#include <cuda_runtime.h>
#include <cuda_bf16.h>
#include <math.h>

#define Nn 1024
#define Qq 32
#define Mm 256
#define Dd 32
#define JITTER 1e-6f
#define TRI (Mm*(Mm+1)/2)

__device__ __forceinline__ int off(int i){ return (i*(i+1))>>1; }

// ---------------- scratch ----------------
__device__ float g_hw1[Nn*Qq];
__device__ float g_wm1[Nn*Qq];
__device__ float g_hw2[Nn*Qq];
__device__ float g_w2[Nn*Qq];
__device__ float g_wm2[Nn*Qq];
__device__ float g_G1[Nn];
__device__ float g_F2[Nn];
__device__ float g_E2[Nn*Mm];
__device__ float g_qmk[Mm*Mm];
__device__ float g_Kmm[Mm*Mm];
__device__ float g_Lp[TRI];
__device__ float g_Ldiag[Mm];
__device__ float g_T128[128*128];
__device__ float g_Kinv[Mm*Mm];
__device__ float g_psi1[Nn*Mm];
__device__ float g_psi2[Mm*Mm];
__device__ float g_psi2p[8*Mm*Mm];
__device__ float g_A1[Nn*Mm];
__device__ float g_R[Mm*Mm*Dd];
__device__ float g_uuT[Mm*Mm];
__device__ float g_uuTp[16*Mm*Mm];
__device__ float g_Gp[8*Mm*Mm];
__device__ float g_P2[Mm*Mm];
__device__ float g_KPK[Mm*Mm];
__device__ float g_G[Mm*Mm];
__device__ float g_tmpF[(size_t)Nn*Mm*Dd];

// ---------------- per-n prep ----------------
__global__ void prep_n_kernel(const float* __restrict__ Xmean,
                              const float* __restrict__ Xvar,
                              const float* __restrict__ ls)
{
    int n = blockIdx.x*blockDim.x + threadIdx.x;
    if (n >= Nn) return;
    float ld1 = 0.f, ld2 = 0.f, a1 = 0.f, a2 = 0.f;
    #pragma unroll
    for (int q = 0; q < Qq; q++){
        float l = ls[q];
        float l2 = l*l;
        float S = Xvar[n*Qq+q];
        float mu = Xmean[n*Qq+q];
        float d1 = l2 + S;
        float d2 = l2 + 2.f*S;
        float w1 = 1.f/d1;
        float w2 = 1.f/d2;
        g_hw1[n*Qq+q] = 0.5f*w1;
        g_hw2[n*Qq+q] = 0.5f*w2;
        g_w2[n*Qq+q]  = w2;
        g_wm1[n*Qq+q] = w1*mu;
        g_wm2[n*Qq+q] = w2*mu;
        ld1 += logf(d1/l2);
        ld2 += logf(d2/l2);
        a1 = fmaf(w1*mu, mu, a1);
        a2 = fmaf(w2*mu, mu, a2);
    }
    g_G1[n] = -0.5f*ld1 - 0.5f*a1;
    g_F2[n] = -0.5f*ld2 - a2;
}

// ---------------- qmk and Kmm ----------------
__global__ void prep_kmm_kernel(const float* __restrict__ Z,
                                const float* __restrict__ ls,
                                const float* __restrict__ var_p)
{
    int idx = blockIdx.x*blockDim.x + threadIdx.x;
    if (idx >= Mm*Mm) return;
    int m = idx / Mm, k = idx % Mm;
    float s = 0.f;
    #pragma unroll
    for (int q = 0; q < Qq; q++){
        float l = ls[q];
        float d = Z[m*Qq+q] - Z[k*Qq+q];
        s += (d*d)/(l*l);
    }
    g_qmk[idx] = s;
    float v = var_p[0];
    g_Kmm[idx] = v*expf(-0.5f*s) + ((m==k)?JITTER:0.f);
}

// ---------------- fused E2 + psi1 ----------------
__global__ void e2psi1_kernel(const float* __restrict__ Z,
                              const float* __restrict__ var_p)
{
    int tx = threadIdx.x, ty = threadIdx.y;
    int m = blockIdx.x*32 + tx;
    int n0 = blockIdx.y*8;
    int n = n0 + ty;
    __shared__ float Zs[32][33];
    __shared__ float w1b[8][32], wm1b[8][32];
    __shared__ float w2b[8][32], wm2b[8][32], gs[8];
    int t = ty*32 + tx;
    for (int i = t; i < 32*Qq; i += 256){
        int r = i/Qq, q = i%Qq;
        Zs[r][q] = Z[(blockIdx.x*32+r)*Qq + q];
    }
    for (int i = t; i < 8*Qq; i += 256){
        int r = i/Qq, q = i%Qq;
        w1b[r][q]  = g_hw1[(n0+r)*Qq + q];
        wm1b[r][q] = g_wm1[(n0+r)*Qq + q];
        w2b[r][q]  = g_w2[(n0+r)*Qq + q];
        wm2b[r][q] = g_wm2[(n0+r)*Qq + q];
    }
    if (t < 8) gs[t] = g_G1[n0+t];
    __syncthreads();
    float s1 = 0.f, s2 = 0.f;
    #pragma unroll
    for (int q = 0; q < Qq; q++){
        float z = Zs[tx][q];
        float t1 = fmaf(-w1b[ty][q], z, wm1b[ty][q]);
        s1 = fmaf(t1, z, s1);
        float t2 = fmaf(-0.25f*w2b[ty][q], z, wm2b[ty][q]);
        s2 = fmaf(t2, z, s2);
    }
    g_psi1[n*Mm + m] = var_p[0]*__expf(gs[ty] + s1);
    g_E2[n*Mm + m] = s2;
}

// ---------------- psi2 ----------------
__global__ void psi2_kernel(const float* __restrict__ Z)
{
    int rem = blockIdx.x, bi = 0;
    for (bi = 0; bi < 16; bi++){ int len = 16-bi; if (rem < len) break; rem -= len; }
    int bj = bi + rem;
    int chunk = blockIdx.y;
    int tx = threadIdx.x, ty = threadIdx.y;
    int m = bi*16 + ty;
    int k = bj*16 + tx;
    int t = ty*16 + tx;

    __shared__ float Zm[16][33], Zk[16][33];
    for (int i = t; i < 16*Qq; i += 256){
        int r = i/Qq, q = i%Qq;
        Zm[r][q] = Z[(bi*16+r)*Qq + q];
        Zk[r][q] = Z[(bj*16+r)*Qq + q];
    }
    __syncthreads();
    float zp[Qq];
    #pragma unroll
    for (int q = 0; q < Qq; q++) zp[q] = Zm[ty][q]*Zk[tx][q];
    float base = -0.25f*g_qmk[m*Mm + k];

    __shared__ float wb[16][33], F2s[16];
    __shared__ float Em[16][17], Ek[16][17];
    float acc = 0.f;
    int nbeg = chunk*(Nn/8), nend = nbeg + Nn/8;
    for (int n0 = nbeg; n0 < nend; n0 += 16){
        __syncthreads();
        for (int i = t; i < 16*Qq; i += 256){
            int r = i/Qq, q = i%Qq;
            wb[r][q] = g_hw2[(n0+r)*Qq + q];
        }
        {
            int nn = t >> 4, r = t & 15;
            Em[nn][r] = g_E2[(n0+nn)*Mm + bi*16 + r];
            Ek[nn][r] = g_E2[(n0+nn)*Mm + bj*16 + r];
        }
        if (t < 16) F2s[t] = g_F2[n0+t];
        __syncthreads();
        #pragma unroll 2
        for (int nn = 0; nn < 16; nn++){
            float dot = 0.f;
            #pragma unroll
            for (int q = 0; q < Qq; q++)
                dot = fmaf(wb[nn][q], zp[q], dot);
            float e = base + F2s[nn] + Em[nn][ty] + Ek[nn][tx] - dot;
            acc += __expf(e);
        }
    }
    g_psi2p[chunk*(Mm*Mm) + m*Mm + k] = acc;
}

__global__ void psi2_combine_kernel(const float* __restrict__ var_p)
{
    int idx = blockIdx.x*blockDim.x + threadIdx.x;
    if (idx >= Mm*Mm) return;
    int m = idx / Mm, k = idx % Mm;
    int src = ((m>>4) <= (k>>4)) ? (m*Mm + k) : (k*Mm + m);
    float s = 0.f;
    #pragma unroll
    for (int c = 0; c < 8; c++) s += g_psi2p[c*(Mm*Mm) + src];
    float v = var_p[0];
    g_psi2[idx] = v*v*s;
}

// ============ Cholesky (1024 thr, rank-4 trailing) + diag inversion + level-1 ============
__global__ void cholinv_kernel()
{
    extern __shared__ float sm[];
    float* sL = sm;            // TRI
    float* Vt = sm + TRI;      // 8448
    __shared__ float col0[Mm], col1[Mm], col2[Mm], col3[Mm];
    int t = threadIdx.x;
    int warp = t >> 5, lane = t & 31;

    for (int idx = t; idx < TRI; idx += 1024){
        int i = (int)((sqrtf(8.f*(float)idx + 1.f) - 1.f)*0.5f);
        while (off(i+1) <= idx) i++;
        while (off(i) > idx) i--;
        int j = idx - off(i);
        sL[idx] = g_Kmm[i*Mm + j];
    }
    __syncthreads();

    for (int k = 0; k < Mm; k += 4){
        // ---- column 0 ----
        if (t == 0) sL[off(k)+k] = sqrtf(sL[off(k)+k]);
        __syncthreads();
        {
            float inv = 1.f/sL[off(k)+k];
            float v = 0.f;
            if (t > k && t < Mm){ v = sL[off(t)+k]*inv; sL[off(t)+k] = v; }
            if (t < Mm) col0[t] = v;
        }
        __syncthreads();
        // ---- column 1 ----
        {
            float tmp = 0.f;
            if (t >= k+1 && t < Mm) tmp = sL[off(t)+(k+1)] - col0[t]*col0[k+1];
            if (t == k+1) sL[off(k+1)+(k+1)] = sqrtf(tmp);
            __syncthreads();
            float inv = 1.f/sL[off(k+1)+(k+1)];
            float v = 0.f;
            if (t > k+1 && t < Mm){ v = tmp*inv; sL[off(t)+(k+1)] = v; }
            if (t < Mm) col1[t] = v;
        }
        __syncthreads();
        // ---- column 2 ----
        {
            float tmp = 0.f;
            if (t >= k+2 && t < Mm)
                tmp = sL[off(t)+(k+2)] - col0[t]*col0[k+2] - col1[t]*col1[k+2];
            if (t == k+2) sL[off(k+2)+(k+2)] = sqrtf(tmp);
            __syncthreads();
            float inv = 1.f/sL[off(k+2)+(k+2)];
            float v = 0.f;
            if (t > k+2 && t < Mm){ v = tmp*inv; sL[off(t)+(k+2)] = v; }
            if (t < Mm) col2[t] = v;
        }
        __syncthreads();
        // ---- column 3 ----
        {
            float tmp = 0.f;
            if (t >= k+3 && t < Mm)
                tmp = sL[off(t)+(k+3)] - col0[t]*col0[k+3] - col1[t]*col1[k+3]
                                       - col2[t]*col2[k+3];
            if (t == k+3) sL[off(k+3)+(k+3)] = sqrtf(tmp);
            __syncthreads();
            float inv = 1.f/sL[off(k+3)+(k+3)];
            float v = 0.f;
            if (t > k+3 && t < Mm){ v = tmp*inv; sL[off(t)+(k+3)] = v; }
            if (t < Mm) col3[t] = v;
        }
        __syncthreads();
        // ---- rank-4 trailing update, j >= k+4 ----
        for (int i = k+4+warp; i < Mm; i += 32){
            float c0 = col0[i], c1 = col1[i], c2 = col2[i], c3 = col3[i];
            int b = off(i);
            for (int j = k+4+lane; j <= i; j += 32)
                sL[b+j] -= c0*col0[j] + c1*col1[j] + c2*col2[j] + c3*col3[j];
        }
        __syncthreads();
    }
    if (t < Mm) g_Ldiag[t] = sL[off(t)+t];
    __syncthreads();

    // invert 8 diagonal 32x32 blocks (warps 0..7)
    if (warp < 8){
        int r0 = warp*32;
        float* V = Vt + warp*1056;
        int c = lane;
        for (int r = 0; r < 32; r++){
            float sum = 0.f;
            for (int k = c; k < r; k++)
                sum = fmaf(sL[off(r0+r)+r0+k], V[k*33+c], sum);
            float diag = sL[off(r0+r)+r0+r];
            float v;
            if (c < r)       v = -sum/diag;
            else if (c == r) v = 1.f/diag;
            else             v = 0.f;
            V[r*33+c] = v;
        }
    }
    __syncthreads();
    {
        int pos = t & 1023;
        int r = pos >> 5, c = pos & 31;
        for (int b = 0; b < 8; b++)
            if (c <= r) sL[off(b*32+r)+b*32+c] = Vt[b*1056 + r*33 + c];
    }
    __syncthreads();

    // level-1 combine: 4 pairs concurrently
    {
        int p  = t >> 8;
        int ti = t & 255;
        int i  = ti >> 3;
        int j0 = (ti & 7)*4;
        int row0 = p*64;
        float acc[4] = {0,0,0,0};
        for (int k = 0; k < 32; k++){
            float b = sL[off(row0+32+i)+row0+k];
            #pragma unroll
            for (int jj = 0; jj < 4; jj++){
                int j = j0+jj;
                if (j <= k) acc[jj] = fmaf(b, sL[off(row0+k)+row0+j], acc[jj]);
            }
        }
        float* Tp = Vt + p*1056;
        #pragma unroll
        for (int jj = 0; jj < 4; jj++) Tp[i*33 + j0+jj] = acc[jj];
        __syncthreads();
        float acc2[4] = {0,0,0,0};
        for (int k = 0; k <= i; k++){
            float cv = sL[off(row0+32+i)+row0+32+k];
            #pragma unroll
            for (int jj = 0; jj < 4; jj++)
                acc2[jj] = fmaf(cv, Tp[k*33 + j0+jj], acc2[jj]);
        }
        #pragma unroll
        for (int jj = 0; jj < 4; jj++)
            sL[off(row0+32+i)+row0+j0+jj] = -acc2[jj];
    }
    __syncthreads();

    for (int idx = t; idx < TRI; idx += 1024) g_Lp[idx] = sL[idx];
}

// ============ level-2 combine (64->128), smem-staged, 2 CTAs ============
__global__ void inv_lvl2_kernel()
{
    extern __shared__ float sm[];
    float* sA = sm;             // 64*65
    float* sB = sm + 4160;      // 64*65
    float* sT = sm + 8320;      // 64*65
    int row0 = blockIdx.x*128;
    int t = threadIdx.x;
    int lr = t >> 2, q = (t & 3)*16;
    for (int c = 0; c < 16; c++){
        int col = q + c;
        sB[lr*65 + col] = g_Lp[off(row0+64+lr) + row0 + col];
        sA[lr*65 + col] = (col <= lr) ? g_Lp[off(row0+lr) + row0 + col] : 0.f;
    }
    __syncthreads();
    int i0 = (t >> 4)*4, j0 = (t & 15)*4;
    float acc[4][4] = {};
    for (int k = 0; k < 64; k++){
        float b[4], a[4];
        #pragma unroll
        for (int ii = 0; ii < 4; ii++) b[ii] = sB[(i0+ii)*65 + k];
        #pragma unroll
        for (int jj = 0; jj < 4; jj++) a[jj] = sA[k*65 + j0+jj];
        #pragma unroll
        for (int ii = 0; ii < 4; ii++)
            #pragma unroll
            for (int jj = 0; jj < 4; jj++)
                acc[ii][jj] = fmaf(b[ii], a[jj], acc[ii][jj]);
    }
    #pragma unroll
    for (int ii = 0; ii < 4; ii++)
        #pragma unroll
        for (int jj = 0; jj < 4; jj++)
            sT[(i0+ii)*65 + j0+jj] = acc[ii][jj];
    __syncthreads();
    for (int c = 0; c < 16; c++){
        int col = q + c;
        sB[lr*65 + col] = (col <= lr) ? g_Lp[off(row0+64+lr) + row0+64 + col] : 0.f;
    }
    __syncthreads();
    float acc2[4][4] = {};
    for (int k = 0; k < 64; k++){
        float cv[4], tv[4];
        #pragma unroll
        for (int ii = 0; ii < 4; ii++) cv[ii] = sB[(i0+ii)*65 + k];
        #pragma unroll
        for (int jj = 0; jj < 4; jj++) tv[jj] = sT[k*65 + j0+jj];
        #pragma unroll
        for (int ii = 0; ii < 4; ii++)
            #pragma unroll
            for (int jj = 0; jj < 4; jj++)
                acc2[ii][jj] = fmaf(cv[ii], tv[jj], acc2[ii][jj]);
    }
    #pragma unroll
    for (int ii = 0; ii < 4; ii++)
        #pragma unroll
        for (int jj = 0; jj < 4; jj++)
            g_Lp[off(row0+64+i0+ii)+row0+j0+jj] = -acc2[ii][jj];
}

// ============ level-3a: T128 = B * Ainv(128), smem-staged, 4 CTAs ============
__global__ void inv_lvl3a_kernel()
{
    __shared__ float sB[64*33];
    __shared__ float sA[32*65];
    int bi = (blockIdx.x >> 1)*64, bj = (blockIdx.x & 1)*64;
    int t = threadIdx.x;
    int i0 = (t >> 4)*4, j0 = (t & 15)*4;
    float acc[4][4] = {};
    for (int kc = 0; kc < 128; kc += 32){
        __syncthreads();
        {
            int lr = t >> 2, q = (t & 3)*8;
            for (int c = 0; c < 8; c++)
                sB[lr*33 + q + c] = g_Lp[off(128 + bi + lr) + kc + q + c];
            int kr = t >> 3, q2 = (t & 7)*8;
            for (int c = 0; c < 8; c++){
                int j = bj + q2 + c;
                sA[kr*65 + q2 + c] = (j <= kc+kr) ? g_Lp[off(kc+kr) + j] : 0.f;
            }
        }
        __syncthreads();
        #pragma unroll
        for (int k = 0; k < 32; k++){
            float b[4], a[4];
            #pragma unroll
            for (int ii = 0; ii < 4; ii++) b[ii] = sB[(i0+ii)*33 + k];
            #pragma unroll
            for (int jj = 0; jj < 4; jj++) a[jj] = sA[k*65 + j0+jj];
            #pragma unroll
            for (int ii = 0; ii < 4; ii++)
                #pragma unroll
                for (int jj = 0; jj < 4; jj++)
                    acc[ii][jj] = fmaf(b[ii], a[jj], acc[ii][jj]);
        }
    }
    #pragma unroll
    for (int ii = 0; ii < 4; ii++)
        #pragma unroll
        for (int jj = 0; jj < 4; jj++)
            g_T128[(bi+i0+ii)*128 + bj+j0+jj] = acc[ii][jj];
}

// ============ level-3b: O = -Cinv(128) * T128, smem-staged, 4 CTAs ============
__global__ void inv_lvl3b_kernel()
{
    __shared__ float sC[64*33];
    __shared__ float sT[32*65];
    int bi = (blockIdx.x >> 1)*64, bj = (blockIdx.x & 1)*64;
    int t = threadIdx.x;
    int i0 = (t >> 4)*4, j0 = (t & 15)*4;
    float acc[4][4] = {};
    for (int kc = 0; kc < 128; kc += 32){
        __syncthreads();
        {
            int lr = t >> 2, q = (t & 3)*8;
            for (int c = 0; c < 8; c++){
                int k = kc + q + c;
                sC[lr*33 + q + c] = (k <= bi+lr) ? g_Lp[off(128 + bi + lr) + 128 + k] : 0.f;
            }
            int kr = t >> 3, q2 = (t & 7)*8;
            for (int c = 0; c < 8; c++)
                sT[kr*65 + q2 + c] = g_T128[(kc+kr)*128 + bj + q2 + c];
        }
        __syncthreads();
        #pragma unroll
        for (int k = 0; k < 32; k++){
            float cv[4], tv[4];
            #pragma unroll
            for (int ii = 0; ii < 4; ii++) cv[ii] = sC[(i0+ii)*33 + k];
            #pragma unroll
            for (int jj = 0; jj < 4; jj++) tv[jj] = sT[k*65 + j0+jj];
            #pragma unroll
            for (int ii = 0; ii < 4; ii++)
                #pragma unroll
                for (int jj = 0; jj < 4; jj++)
                    acc[ii][jj] = fmaf(cv[ii], tv[jj], acc[ii][jj]);
        }
    }
    #pragma unroll
    for (int ii = 0; ii < 4; ii++)
        #pragma unroll
        for (int jj = 0; jj < 4; jj++)
            g_Lp[off(128+bi+i0+ii) + bj+j0+jj] = -acc[ii][jj];
}

// ============ Kinv = Linv^T Linv directly from packed g_Lp ============
__global__ void kinv_kernel()
{
    const int BM = 64, BN = 64, BK = 16;
    __shared__ float As[BK][BM+1];
    __shared__ float Bs[BK][BN+1];
    int bm = blockIdx.y*BM, bn = blockIdx.x*BN;
    int tid = threadIdx.x;
    int tm = (tid/16)*4, tn = (tid%16)*4;
    int kstart = ((bm > bn ? bm : bn)/BK)*BK;
    float acc[4][4] = {};
    for (int k0 = kstart; k0 < Mm; k0 += BK){
        for (int i = tid; i < BM*BK; i += 256){
            int kk = i/BM, mm = i%BM;
            int gk = k0+kk, gm = bm+mm;
            As[kk][mm] = (gm <= gk) ? g_Lp[off(gk)+gm] : 0.f;
        }
        for (int i = tid; i < BN*BK; i += 256){
            int kk = i/BN, nn = i%BN;
            int gk = k0+kk, gn = bn+nn;
            Bs[kk][nn] = (gn <= gk) ? g_Lp[off(gk)+gn] : 0.f;
        }
        __syncthreads();
        #pragma unroll
        for (int kk = 0; kk < BK; kk++){
            float ra[4], rb[4];
            #pragma unroll
            for (int i = 0; i < 4; i++){ ra[i] = As[kk][tm+i]; rb[i] = Bs[kk][tn+i]; }
            #pragma unroll
            for (int i = 0; i < 4; i++)
                #pragma unroll
                for (int j = 0; j < 4; j++)
                    acc[i][j] = fmaf(ra[i], rb[j], acc[i][j]);
        }
        __syncthreads();
    }
    #pragma unroll
    for (int i = 0; i < 4; i++)
        #pragma unroll
        for (int j = 0; j < 4; j++)
            g_Kinv[(bm+tm+i)*Mm + bn+tn+j] = acc[i][j];
}

// ---------------- masked R ----------------
__global__ void maskR_kernel(const float* __restrict__ qs)
{
    int idx = blockIdx.x*blockDim.x + threadIdx.x;
    if (idx >= Mm*Mm*Dd) return;
    int a = idx / (Mm*Dd);
    int b = (idx / Dd) % Mm;
    g_R[idx] = (b <= a) ? qs[idx] : 0.f;
}

// ---------------- 64x64 SGEMM ----------------
template<int TA, int TB>
__global__ void sgemm(int M_, int N_, int K_,
                      const float* __restrict__ A, int lda,
                      const float* __restrict__ B, int ldb,
                      float* __restrict__ C, int ldc,
                      float alpha, float beta)
{
    const int BM = 64, BN = 64, BK = 16;
    __shared__ float As[BK][BM+1];
    __shared__ float Bs[BK][BN+1];
    int bm = blockIdx.y*BM, bn = blockIdx.x*BN;
    int tid = threadIdx.x;
    int tm = (tid/16)*4, tn = (tid%16)*4;
    float acc[4][4] = {};
    for (int k0 = 0; k0 < K_; k0 += BK){
        if (!TA){
            for (int i = tid; i < BM*BK; i += 256){
                int kk = i%BK, mm = i/BK;
                int gm = bm+mm, gk = k0+kk;
                As[kk][mm] = (gm < M_ && gk < K_) ? A[(size_t)gm*lda + gk] : 0.f;
            }
        } else {
            for (int i = tid; i < BM*BK; i += 256){
                int mm = i%BM, kk = i/BM;
                int gm = bm+mm, gk = k0+kk;
                As[kk][mm] = (gm < M_ && gk < K_) ? A[(size_t)gk*lda + gm] : 0.f;
            }
        }
        if (!TB){
            for (int i = tid; i < BN*BK; i += 256){
                int nn = i%BN, kk = i/BN;
                int gn = bn+nn, gk = k0+kk;
                Bs[kk][nn] = (gn < N_ && gk < K_) ? B[(size_t)gk*ldb + gn] : 0.f;
            }
        } else {
            for (int i = tid; i < BN*BK; i += 256){
                int kk = i%BK, nn = i/BK;
                int gn = bn+nn, gk = k0+kk;
                Bs[kk][nn] = (gn < N_ && gk < K_) ? B[(size_t)gn*ldb + gk] : 0.f;
            }
        }
        __syncthreads();
        #pragma unroll
        for (int kk = 0; kk < BK; kk++){
            float ra[4], rb[4];
            #pragma unroll
            for (int i = 0; i < 4; i++){ ra[i] = As[kk][tm+i]; rb[i] = Bs[kk][tn+i]; }
            #pragma unroll
            for (int i = 0; i < 4; i++)
                #pragma unroll
                for (int j = 0; j < 4; j++)
                    acc[i][j] = fmaf(ra[i], rb[j], acc[i][j]);
        }
        __syncthreads();
    }
    #pragma unroll
    for (int i = 0; i < 4; i++){
        int gm = bm + tm + i;
        if (gm >= M_) continue;
        #pragma unroll
        for (int j = 0; j < 4; j++){
            int gn = bn + tn + j;
            if (gn >= N_) continue;
            float prev = (beta != 0.f) ? C[(size_t)gm*ldc + gn] : 0.f;
            C[(size_t)gm*ldc + gn] = alpha*acc[i][j] + beta*prev;
        }
    }
}

// ---------------- 128x128 SGEMM, 8x8/thread, split-K, caps ----------------
template<int TA, int TB, int CAP>
__global__ void sgemm128(int M_, int N_, int K_, int Kchunk,
                         const float* __restrict__ A, int lda,
                         const float* __restrict__ B, int ldb,
                         float* __restrict__ C, int ldc, size_t partStride)
{
    const int BM = 128, BN = 128, BK = 16;
    __shared__ float As[BK][BM+4];
    __shared__ float Bs[BK][BN+4];
    int bm = blockIdx.y*BM, bn = blockIdx.x*BN;
    int kbeg = blockIdx.z*Kchunk;
    int kend = kbeg + Kchunk; if (kend > K_) kend = K_;
    if (CAP == 1){
        int cap = ((bm < bn ? bm : bn) + BM)*Dd;
        if (kend > cap) kend = cap;
    }
    if (CAP == 2){
        int kb = (bn >> 5) & ~(BK-1);
        if (kbeg < kb) kbeg = kb;
    }
    float* Cb = C + (size_t)blockIdx.z*partStride;
    int tid = threadIdx.x;
    int tm = (tid/16)*8, tn = (tid%16)*8;
    float acc[8][8] = {};
    for (int k0 = kbeg; k0 < kend; k0 += BK){
        if (!TA){
            #pragma unroll
            for (int i = tid; i < BM*BK; i += 256){
                int kk = i%BK, mm = i/BK;
                As[kk][mm] = A[(size_t)(bm+mm)*lda + (k0+kk)];
            }
        } else {
            #pragma unroll
            for (int i = tid; i < BM*BK; i += 256){
                int mm = i%BM, kk = i/BM;
                As[kk][mm] = A[(size_t)(k0+kk)*lda + (bm+mm)];
            }
        }
        if (!TB){
            #pragma unroll
            for (int i = tid; i < BN*BK; i += 256){
                int nn = i%BN, kk = i/BN;
                Bs[kk][nn] = B[(size_t)(k0+kk)*ldb + (bn+nn)];
            }
        } else {
            #pragma unroll
            for (int i = tid; i < BN*BK; i += 256){
                int kk = i%BK, nn = i/BK;
                Bs[kk][nn] = B[(size_t)(bn+nn)*ldb + (k0+kk)];
            }
        }
        __syncthreads();
        #pragma unroll
        for (int kk = 0; kk < BK; kk++){
            float ra[8], rb[8];
            *(float4*)&ra[0] = *(const float4*)&As[kk][tm];
            *(float4*)&ra[4] = *(const float4*)&As[kk][tm+4];
            *(float4*)&rb[0] = *(const float4*)&Bs[kk][tn];
            *(float4*)&rb[4] = *(const float4*)&Bs[kk][tn+4];
            #pragma unroll
            for (int i = 0; i < 8; i++)
                #pragma unroll
                for (int j = 0; j < 8; j++)
                    acc[i][j] = fmaf(ra[i], rb[j], acc[i][j]);
        }
        __syncthreads();
    }
    #pragma unroll
    for (int i = 0; i < 8; i++){
        float* cp = Cb + (size_t)(bm+tm+i)*ldc + bn + tn;
        *(float4*)cp       = *(float4*)&acc[i][0];
        *(float4*)(cp + 4) = *(float4*)&acc[i][4];
    }
}

// ---------------- sum split-K partials ----------------
__global__ void reduce_parts_kernel(float* __restrict__ out,
                                    const float* __restrict__ parts,
                                    int S, int MN, int addBase)
{
    int idx = blockIdx.x*blockDim.x + threadIdx.x;
    if (idx >= MN) return;
    float s = addBase ? out[idx] : 0.f;
    for (int i = 0; i < S; i++) s += parts[(size_t)i*MN + idx];
    out[idx] = s;
}

// ---------------- batched SYRK for forward_var (float4) ----------------
__global__ void var_kernel(float* __restrict__ out_var, const float* __restrict__ beta_p)
{
    __shared__ __align__(16) float T[Mm*Dd];
    int n = blockIdx.x;
    int t = threadIdx.x;
    {
        const float4* src = (const float4*)(g_tmpF + (size_t)n*(Mm*Dd));
        float4* dst = (float4*)T;
        for (int i = t; i < (Mm*Dd)/4; i += 256) dst[i] = src[i];
    }
    __syncthreads();
    float invb = 1.f/beta_p[0];
    int e = t & 31, d0 = (t >> 5)*4;
    float a0=0.f, a1=0.f, a2=0.f, a3=0.f;
    #pragma unroll 4
    for (int m = 0; m < Mm; m++){
        float te = T[m*32 + e];
        float4 td = *(const float4*)&T[m*32 + d0];
        a0 = fmaf(td.x, te, a0);
        a1 = fmaf(td.y, te, a1);
        a2 = fmaf(td.z, te, a2);
        a3 = fmaf(td.w, te, a3);
    }
    float* vp = out_var + (size_t)n*Dd*Dd;
    vp[(d0+0)*32 + e] = a0 + ((d0+0)==e ? invb : 0.f);
    vp[(d0+1)*32 + e] = a1 + ((d0+1)==e ? invb : 0.f);
    vp[(d0+2)*32 + e] = a2 + ((d0+2)==e ? invb : 0.f);
    vp[(d0+3)*32 + e] = a3 + ((d0+3)==e ? invb : 0.f);
}

// ---------------- final scalar reduction -> lml ----------------
__global__ void reduce_lml_kernel(float* __restrict__ out_lml,
                                  const float* __restrict__ var_p,
                                  const float* __restrict__ beta_p,
                                  const float* __restrict__ qs)
{
    __shared__ double red[256];
    int t = threadIdx.x;
    double a1=0, a2=0, a3=0, a4=0, a5=0, a6=0;
    for (int i = t; i < Mm*Mm; i += 256){
        double kv = g_Kinv[i], uu = g_uuT[i];
        a1 += kv*(double)g_psi2[i];
        a2 += kv*uu;
        a3 += (double)g_KPK[i]*uu;
        a4 += (double)g_G[i]*uu;
    }
    for (int i = t; i < Mm; i += 256) a5 += log((double)g_Ldiag[i]);
    for (int i = t; i < Mm*Dd; i += 256){
        int mm = i/Dd, dd = i%Dd;
        double x = (double)qs[(size_t)mm*Mm*Dd + (size_t)mm*Dd + dd];
        a6 += log(x*x);
    }
    double sums[6] = {a1,a2,a3,a4,a5,a6};
    double res[6];
    for (int s = 0; s < 6; s++){
        red[t] = sums[s];
        __syncthreads();
        for (int w = 128; w > 0; w >>= 1){
            if (t < w) red[t] += red[t+w];
            __syncthreads();
        }
        res[s] = red[0];
        __syncthreads();
    }
    if (t == 0){
        double variance = var_p[0], beta = beta_p[0];
        double psi0 = (double)Nn*variance;
        double lml = -0.5*beta*(double)Dd*(psi0 - res[0]);
        double logdetK = 2.0*res[4];
        double kl = 0.5*(res[1] - (double)(Mm*Dd) + (double)Dd*logdetK - res[5]);
        lml -= kl;
        lml -= 0.5*beta*(res[2] - res[3]);
        out_lml[0] = (float)lml;
    }
}

// ---------------- host launcher (R5 topology + eR split) ----------------
extern "C" void kernel_launch(void* const* d_in, const int* in_sizes, int n_in,
                              void* d_out, int out_size)
{
    const float* Xmean = (const float*)d_in[0];
    const float* Xvar  = (const float*)d_in[1];
    const float* Z     = (const float*)d_in[2];
    const float* qmu   = (const float*)d_in[3];
    const float* qs    = (const float*)d_in[4];
    const float* ls    = (const float*)d_in[5];
    const float* var_p = (const float*)d_in[6];
    const float* beta_p= (const float*)d_in[7];

    float* out      = (float*)d_out;
    float* out_mean = out;
    float* out_var  = out + Nn*Dd;
    float* out_lml  = out + Nn*Dd + (size_t)Nn*Dd*Dd;

    float *pPsi1, *pKinv, *pA1, *pR, *puuT, *puuTp, *pGp, *pP2, *pKPK, *pG, *pTmpF, *pPsi2;
    cudaGetSymbolAddress((void**)&pPsi1, g_psi1);
    cudaGetSymbolAddress((void**)&pKinv, g_Kinv);
    cudaGetSymbolAddress((void**)&pA1,   g_A1);
    cudaGetSymbolAddress((void**)&pR,    g_R);
    cudaGetSymbolAddress((void**)&puuT,  g_uuT);
    cudaGetSymbolAddress((void**)&puuTp, g_uuTp);
    cudaGetSymbolAddress((void**)&pGp,   g_Gp);
    cudaGetSymbolAddress((void**)&pP2,   g_P2);
    cudaGetSymbolAddress((void**)&pKPK,  g_KPK);
    cudaGetSymbolAddress((void**)&pG,    g_G);
    cudaGetSymbolAddress((void**)&pTmpF, g_tmpF);
    cudaGetSymbolAddress((void**)&pPsi2, g_psi2);

    const int CHOLINV_SMEM = (TRI + 8448)*4;   // 165376 B
    const int LVL2_SMEM = 3*4160*4;            // 49920 B
    cudaFuncSetAttribute(cholinv_kernel, cudaFuncAttributeMaxDynamicSharedMemorySize, CHOLINV_SMEM);
    cudaFuncSetAttribute(inv_lvl2_kernel, cudaFuncAttributeMaxDynamicSharedMemorySize, LVL2_SMEM);

    static cudaStream_t s1 = nullptr, s2 = nullptr;
    static cudaEvent_t e0 = nullptr, eR = nullptr, e1 = nullptr, e2 = nullptr,
                       e3 = nullptr, e4 = nullptr;
    if (!s1){
        cudaStreamCreateWithFlags(&s1, cudaStreamNonBlocking);
        cudaStreamCreateWithFlags(&s2, cudaStreamNonBlocking);
        cudaEventCreateWithFlags(&e0, cudaEventDisableTiming);
        cudaEventCreateWithFlags(&eR, cudaEventDisableTiming);
        cudaEventCreateWithFlags(&e1, cudaEventDisableTiming);
        cudaEventCreateWithFlags(&e2, cudaEventDisableTiming);
        cudaEventCreateWithFlags(&e3, cudaEventDisableTiming);
        cudaEventCreateWithFlags(&e4, cudaEventDisableTiming);
    }

    // ---- common prep on origin ----
    prep_n_kernel<<<(Nn+255)/256, 256>>>(Xmean, Xvar, ls);
    prep_kmm_kernel<<<(Mm*Mm+255)/256, 256>>>(Z, ls, var_p);
    cudaEventRecord(e0, 0);

    // ---- branch s1: Cholesky + block inversion chain ----
    cudaStreamWaitEvent(s1, e0, 0);
    cholinv_kernel<<<1, 1024, CHOLINV_SMEM, s1>>>();
    inv_lvl2_kernel<<<2, 256, LVL2_SMEM, s1>>>();
    inv_lvl3a_kernel<<<4, 256, 0, s1>>>();
    inv_lvl3b_kernel<<<4, 256, 0, s1>>>();
    {
        dim3 g((Mm+63)/64, (Mm+63)/64);
        kinv_kernel<<<g, 256, 0, s1>>>();
    }
    cudaEventRecord(e1, s1);

    // ---- branch s2: R (eR) then uuT chain (e2) ----
    cudaStreamWaitEvent(s2, e0, 0);
    maskR_kernel<<<(Mm*Mm*Dd+255)/256, 256, 0, s2>>>(qs);
    cudaEventRecord(eR, s2);
    {
        dim3 g((Mm+63)/64, (Mm+63)/64);
        sgemm<0,1><<<g, 256, 0, s2>>>(Mm, Mm, Dd, qmu, Dd, qmu, Dd, puuT, Mm, 1.f, 0.f);
        dim3 g2(Mm/128, Mm/128, 16);
        sgemm128<0,1,1><<<g2, 256, 0, s2>>>(Mm, Mm, Mm*Dd, (Mm*Dd)/16, pR, Mm*Dd, pR, Mm*Dd,
                                            puuTp, Mm, (size_t)Mm*Mm);
        reduce_parts_kernel<<<(Mm*Mm+255)/256, 256, 0, s2>>>(puuT, puuTp, 16, Mm*Mm, 1);
    }
    cudaEventRecord(e2, s2);

    // ---- origin: psi chain ----
    {
        dim3 b(32,8), g(Mm/32, Nn/8);
        e2psi1_kernel<<<g, b>>>(Z, var_p);
    }
    {
        dim3 b(16,16), g(136, 8);
        psi2_kernel<<<g, b>>>(Z);
        psi2_combine_kernel<<<(Mm*Mm+255)/256, 256>>>(var_p);
    }

    // ---- join Kinv, compute A1 ----
    cudaStreamWaitEvent(0, e1, 0);
    {
        dim3 g((Mm+63)/64, (Nn+63)/64);
        sgemm<0,0><<<g, 256>>>(Nn, Mm, Mm, pPsi1, Mm, pKinv, Mm, pA1, Mm, 1.f, 0.f);
    }
    cudaEventRecord(e3, 0);

    // ---- s1 post-A1: mean, P2, KPK, G ----
    cudaStreamWaitEvent(s1, e3, 0);
    {
        dim3 g((Dd+63)/64, (Nn+63)/64);
        sgemm<0,0><<<g, 256, 0, s1>>>(Nn, Dd, Mm, pA1, Mm, qmu, Dd, out_mean, Dd, 1.f, 0.f);
    }
    {
        dim3 g((Mm+63)/64, (Mm+63)/64);
        sgemm<0,0><<<g, 256, 0, s1>>>(Mm, Mm, Mm, pKinv, Mm, pPsi2, Mm, pP2, Mm, 1.f, 0.f);
        sgemm<0,0><<<g, 256, 0, s1>>>(Mm, Mm, Mm, pP2, Mm, pKinv, Mm, pKPK, Mm, 1.f, 0.f);
    }
    {
        dim3 g(Mm/128, Mm/128, 8);
        sgemm128<1,0,0><<<g, 256, 0, s1>>>(Mm, Mm, Nn, Nn/8, pA1, Mm, pA1, Mm,
                                           pGp, Mm, (size_t)Mm*Mm);
        reduce_parts_kernel<<<(Mm*Mm+255)/256, 256, 0, s1>>>(pG, pGp, 8, Mm*Mm, 0);
    }
    cudaEventRecord(e4, s1);

    // ---- origin: tmpF (needs only R) -> var ----
    cudaStreamWaitEvent(0, eR, 0);
    {
        dim3 g((Mm*Dd)/128, Nn/128, 1);
        sgemm128<0,0,2><<<g, 256>>>(Nn, Mm*Dd, Mm, Mm, pA1, Mm, pR, Mm*Dd,
                                    pTmpF, Mm*Dd, 0);
    }
    var_kernel<<<Nn, 256>>>(out_var, beta_p);

    // ---- final join: needs uuT (e2) and s1 chain (e4) ----
    cudaStreamWaitEvent(0, e2, 0);
    cudaStreamWaitEvent(0, e4, 0);
    reduce_lml_kernel<<<1, 256>>>(out_lml, var_p, beta_p, qs);
}